// round 1
// baseline (speedup 1.0000x reference)
#include <cuda_runtime.h>

// Problem constants
#define B_   4
#define T_   2048
#define E_   1024
#define H_   16
#define HS_  64
#define DFF_ 4096
#define M_   (B_ * T_)   // 8192 rows

// ---------------------------------------------------------------------------
// Scratch (device globals — no allocation allowed in kernel_launch)
// ---------------------------------------------------------------------------
__device__ float g_h   [(size_t)M_ * E_];    // ln1 output
__device__ float g_q   [(size_t)M_ * E_];
__device__ float g_k   [(size_t)M_ * E_];
__device__ float g_v   [(size_t)M_ * E_];
__device__ float g_attn[(size_t)M_ * E_];    // attention output (pre-proj)
__device__ float g_h2  [(size_t)M_ * E_];    // ln2 output
__device__ float g_ff  [(size_t)M_ * DFF_];  // relu(h2@W1+b1)

// ---------------------------------------------------------------------------
// LayerNorm: one block per row of E_=1024, 256 threads, float4 per thread
// ---------------------------------------------------------------------------
__global__ __launch_bounds__(256)
void ln_kernel(const float* __restrict__ in, const float* __restrict__ gamma,
               const float* __restrict__ beta, float* __restrict__ out) {
    int row = blockIdx.x;
    int t = threadIdx.x;
    const float4* inr = (const float4*)(in + (size_t)row * E_);
    float4 v = inr[t];

    float s1 = v.x + v.y + v.z + v.w;
    float s2 = v.x * v.x + v.y * v.y + v.z * v.z + v.w * v.w;
    #pragma unroll
    for (int o = 16; o > 0; o >>= 1) {
        s1 += __shfl_xor_sync(0xffffffffu, s1, o);
        s2 += __shfl_xor_sync(0xffffffffu, s2, o);
    }
    __shared__ float red[64];
    int lane = t & 31, w = t >> 5;
    if (lane == 0) { red[w] = s1; red[w + 32] = s2; }
    __syncthreads();
    float ts1 = 0.f, ts2 = 0.f;
    #pragma unroll
    for (int i = 0; i < 8; i++) { ts1 += red[i]; ts2 += red[i + 32]; }

    float mu  = ts1 * (1.0f / E_);
    float var = ts2 * (1.0f / E_) - mu * mu;
    float rs  = rsqrtf(var + 1e-5f);

    float4 g4 = ((const float4*)gamma)[t];
    float4 b4 = ((const float4*)beta)[t];
    float4 o4;
    o4.x = (v.x - mu) * rs * g4.x + b4.x;
    o4.y = (v.y - mu) * rs * g4.y + b4.y;
    o4.z = (v.z - mu) * rs * g4.z + b4.z;
    o4.w = (v.w - mu) * rs * g4.w + b4.w;
    ((float4*)(out + (size_t)row * E_))[t] = o4;
}

// ---------------------------------------------------------------------------
// SGEMM: C = A[M,K] @ B[K,N] + bias[N] (+relu | +res)
// 128x128 block tile, BK=8, 8x8 per thread, 256 threads, double-buffered smem
// EPI: 0 = bias, 1 = bias+relu, 2 = bias+residual
// ---------------------------------------------------------------------------
template<int EPI>
__global__ __launch_bounds__(256)
void sgemm_kernel(const float* __restrict__ A, const float* __restrict__ Bm,
                  const float* __restrict__ bias, const float* __restrict__ res,
                  float* __restrict__ C, int M, int N, int K) {
    __shared__ float As[2][8][128];   // k-major: As[k][m]
    __shared__ float Bs[2][8][128];   // Bs[k][n]

    int tid = threadIdx.x;
    int m0 = blockIdx.y * 128;
    int n0 = blockIdx.x * 128;

    // Global load mapping
    int arow = tid >> 1;            // 0..127
    int acol = (tid & 1) * 4;       // 0 or 4
    int brow = tid >> 5;            // 0..7
    int bcol = (tid & 31) * 4;      // 0..124

    const float* Ag = A  + (size_t)(m0 + arow) * K + acol;
    const float* Bg = Bm + (size_t)brow * N + n0 + bcol;

    // Initial tile into buffer 0
    float4 pa = *(const float4*)Ag;
    float4 pb = *(const float4*)Bg;
    As[0][acol + 0][arow] = pa.x;
    As[0][acol + 1][arow] = pa.y;
    As[0][acol + 2][arow] = pa.z;
    As[0][acol + 3][arow] = pa.w;
    *(float4*)&Bs[0][brow][bcol] = pb;
    __syncthreads();

    int tx = tid & 15, ty = tid >> 4;
    float Cr[8][8] = {};
    float ar[8], br[8];

    int nt = K >> 3;
    for (int kt = 0; kt < nt; kt++) {
        int cur = kt & 1;
        if (kt + 1 < nt) {
            pa = *(const float4*)(Ag + (kt + 1) * 8);
            pb = *(const float4*)(Bg + (size_t)(kt + 1) * 8 * N);
        }
        #pragma unroll
        for (int k = 0; k < 8; k++) {
            *(float4*)&ar[0] = *(const float4*)&As[cur][k][ty * 8];
            *(float4*)&ar[4] = *(const float4*)&As[cur][k][ty * 8 + 4];
            *(float4*)&br[0] = *(const float4*)&Bs[cur][k][tx * 8];
            *(float4*)&br[4] = *(const float4*)&Bs[cur][k][tx * 8 + 4];
            #pragma unroll
            for (int i = 0; i < 8; i++)
                #pragma unroll
                for (int j = 0; j < 8; j++)
                    Cr[i][j] += ar[i] * br[j];
        }
        if (kt + 1 < nt) {
            int nxt = cur ^ 1;
            As[nxt][acol + 0][arow] = pa.x;
            As[nxt][acol + 1][arow] = pa.y;
            As[nxt][acol + 2][arow] = pa.z;
            As[nxt][acol + 3][arow] = pa.w;
            *(float4*)&Bs[nxt][brow][bcol] = pb;
            __syncthreads();
        }
    }

    // Epilogue
    #pragma unroll
    for (int i = 0; i < 8; i++) {
        int row = m0 + ty * 8 + i;
        #pragma unroll
        for (int j = 0; j < 8; j += 4) {
            int col = n0 + tx * 8 + j;
            float4 bv = *(const float4*)&bias[col];
            float4 o;
            o.x = Cr[i][j + 0] + bv.x;
            o.y = Cr[i][j + 1] + bv.y;
            o.z = Cr[i][j + 2] + bv.z;
            o.w = Cr[i][j + 3] + bv.w;
            if (EPI == 1) {
                o.x = fmaxf(o.x, 0.f); o.y = fmaxf(o.y, 0.f);
                o.z = fmaxf(o.z, 0.f); o.w = fmaxf(o.w, 0.f);
            }
            if (EPI == 2) {
                float4 rv = *(const float4*)&res[(size_t)row * N + col];
                o.x += rv.x; o.y += rv.y; o.z += rv.z; o.w += rv.w;
            }
            *(float4*)&C[(size_t)row * N + col] = o;
        }
    }
}

// ---------------------------------------------------------------------------
// Causal flash attention, fp32. One block = (b, h, 64-row q tile), 256 threads.
// smem: Qt[d][r], Kt[d][c], Vs[c][d], Pt[c][r]  all stride 68 (16B-aligned pad)
// Thread (ty,tx) owns 4x4 register tiles of S (rows/cols) and O (rows/dims).
// ---------------------------------------------------------------------------
#define ASTRIDE 68
#define ATTN_SMEM (4 * 64 * ASTRIDE * (int)sizeof(float))   // 69632 bytes

__global__ __launch_bounds__(256)
void attn_kernel(const float* __restrict__ Q, const float* __restrict__ Kg,
                 const float* __restrict__ Vg, float* __restrict__ Og) {
    extern __shared__ float sm[];
    float* Qt = sm;                   // [64][68] : Qt[d*68 + r]
    float* Kt = sm + 64 * ASTRIDE;    // Kt[d*68 + c]
    float* Vs = sm + 2 * 64 * ASTRIDE;// Vs[c*68 + d]
    float* Pt = sm + 3 * 64 * ASTRIDE;// Pt[c*68 + r]

    int tid = threadIdx.x;
    int q0 = blockIdx.x * 64;
    int bh = blockIdx.y;
    int b = bh >> 4, h = bh & 15;
    const float scale = 0.125f;       // HS^-0.5

    size_t base = ((size_t)b * T_) * E_ + (size_t)h * HS_;

    // Load Q tile transposed (scaled)
    for (int e = tid; e < 64 * 16; e += 256) {
        int r = e >> 4, d4 = (e & 15) * 4;
        float4 v = *(const float4*)(Q + base + (size_t)(q0 + r) * E_ + d4);
        Qt[(d4 + 0) * ASTRIDE + r] = v.x * scale;
        Qt[(d4 + 1) * ASTRIDE + r] = v.y * scale;
        Qt[(d4 + 2) * ASTRIDE + r] = v.z * scale;
        Qt[(d4 + 3) * ASTRIDE + r] = v.w * scale;
    }

    int tx = tid & 15, ty = tid >> 4;
    int r0 = ty * 4, c0 = tx * 4;

    float Oc[4][4] = {};
    float mrow[4] = {-1e30f, -1e30f, -1e30f, -1e30f};
    float lrow[4] = {};

    int ntiles = (q0 >> 6) + 1;
    for (int jt = 0; jt < ntiles; jt++) {
        int k0 = jt * 64;
        __syncthreads();   // previous iteration done with Kt/Vs/Pt
        // Load K transposed, V direct
        for (int e = tid; e < 64 * 16; e += 256) {
            int r = e >> 4, d4 = (e & 15) * 4;
            float4 kv = *(const float4*)(Kg + base + (size_t)(k0 + r) * E_ + d4);
            Kt[(d4 + 0) * ASTRIDE + r] = kv.x;
            Kt[(d4 + 1) * ASTRIDE + r] = kv.y;
            Kt[(d4 + 2) * ASTRIDE + r] = kv.z;
            Kt[(d4 + 3) * ASTRIDE + r] = kv.w;
            float4 vv = *(const float4*)(Vg + base + (size_t)(k0 + r) * E_ + d4);
            *(float4*)&Vs[r * ASTRIDE + d4] = vv;
        }
        __syncthreads();

        // S = Q K^T (scaled), 4x4 per thread
        float Sc[4][4] = {};
        #pragma unroll 8
        for (int d = 0; d < 64; d++) {
            float4 qv = *(const float4*)&Qt[d * ASTRIDE + r0];
            float4 kv = *(const float4*)&Kt[d * ASTRIDE + c0];
            float qa[4] = {qv.x, qv.y, qv.z, qv.w};
            float ka[4] = {kv.x, kv.y, kv.z, kv.w};
            #pragma unroll
            for (int i = 0; i < 4; i++)
                #pragma unroll
                for (int j = 0; j < 4; j++)
                    Sc[i][j] += qa[i] * ka[j];
        }

        // Causal mask on the diagonal tile (k0 == q0)
        if (jt == ntiles - 1) {
            #pragma unroll
            for (int i = 0; i < 4; i++)
                #pragma unroll
                for (int j = 0; j < 4; j++)
                    if (c0 + j > r0 + i) Sc[i][j] = -1e30f;
        }

        // Online softmax: row max / rescale / exp / row sum (16-lane shfl groups)
        float mnew[4], al[4];
        #pragma unroll
        for (int i = 0; i < 4; i++) {
            float mx = fmaxf(fmaxf(Sc[i][0], Sc[i][1]), fmaxf(Sc[i][2], Sc[i][3]));
            #pragma unroll
            for (int o = 8; o > 0; o >>= 1)
                mx = fmaxf(mx, __shfl_xor_sync(0xffffffffu, mx, o));
            mnew[i] = fmaxf(mrow[i], mx);
            al[i] = __expf(mrow[i] - mnew[i]);
            mrow[i] = mnew[i];
        }
        #pragma unroll
        for (int i = 0; i < 4; i++) {
            float s = 0.f;
            #pragma unroll
            for (int j = 0; j < 4; j++) {
                Sc[i][j] = __expf(Sc[i][j] - mnew[i]);
                s += Sc[i][j];
            }
            #pragma unroll
            for (int o = 8; o > 0; o >>= 1)
                s += __shfl_xor_sync(0xffffffffu, s, o);
            lrow[i] = lrow[i] * al[i] + s;
            #pragma unroll
            for (int j = 0; j < 4; j++) Oc[i][j] *= al[i];
        }

        // Stage P transposed for the PV GEMM
        #pragma unroll
        for (int i = 0; i < 4; i++)
            #pragma unroll
            for (int j = 0; j < 4; j++)
                Pt[(c0 + j) * ASTRIDE + (r0 + i)] = Sc[i][j];
        __syncthreads();

        // O += P V
        #pragma unroll 8
        for (int c = 0; c < 64; c++) {
            float4 pv = *(const float4*)&Pt[c * ASTRIDE + r0];
            float4 vv = *(const float4*)&Vs[c * ASTRIDE + c0];
            float pa[4] = {pv.x, pv.y, pv.z, pv.w};
            float va[4] = {vv.x, vv.y, vv.z, vv.w};
            #pragma unroll
            for (int i = 0; i < 4; i++)
                #pragma unroll
                for (int j = 0; j < 4; j++)
                    Oc[i][j] += pa[i] * va[j];
        }
    }

    // Normalize + write
    #pragma unroll
    for (int i = 0; i < 4; i++) {
        float inv = 1.0f / lrow[i];
        float4 o;
        o.x = Oc[i][0] * inv;
        o.y = Oc[i][1] * inv;
        o.z = Oc[i][2] * inv;
        o.w = Oc[i][3] * inv;
        *(float4*)(Og + base + (size_t)(q0 + r0 + i) * E_ + c0) = o;
    }
}

// ---------------------------------------------------------------------------
// Launch
// ---------------------------------------------------------------------------
extern "C" void kernel_launch(void* const* d_in, const int* in_sizes, int n_in,
                              void* d_out, int out_size) {
    (void)in_sizes; (void)n_in; (void)out_size;
    const float* x     = (const float*)d_in[0];
    const float* ln1_g = (const float*)d_in[1];
    const float* ln1_b = (const float*)d_in[2];
    const float* Wq    = (const float*)d_in[3];
    const float* bq    = (const float*)d_in[4];
    const float* Wk    = (const float*)d_in[5];
    const float* bk    = (const float*)d_in[6];
    const float* Wv    = (const float*)d_in[7];
    const float* bv    = (const float*)d_in[8];
    const float* Wp    = (const float*)d_in[9];
    const float* bp    = (const float*)d_in[10];
    const float* ln2_g = (const float*)d_in[11];
    const float* ln2_b = (const float*)d_in[12];
    const float* W1    = (const float*)d_in[13];
    const float* b1    = (const float*)d_in[14];
    const float* W2    = (const float*)d_in[15];
    const float* b2    = (const float*)d_in[16];
    float* out = (float*)d_out;

    float *h, *q, *k, *v, *attn, *h2, *ff;
    cudaGetSymbolAddress((void**)&h,    g_h);
    cudaGetSymbolAddress((void**)&q,    g_q);
    cudaGetSymbolAddress((void**)&k,    g_k);
    cudaGetSymbolAddress((void**)&v,    g_v);
    cudaGetSymbolAddress((void**)&attn, g_attn);
    cudaGetSymbolAddress((void**)&h2,   g_h2);
    cudaGetSymbolAddress((void**)&ff,   g_ff);

    cudaFuncSetAttribute(attn_kernel,
                         cudaFuncAttributeMaxDynamicSharedMemorySize, ATTN_SMEM);

    // 1) ln1
    ln_kernel<<<M_, 256>>>(x, ln1_g, ln1_b, h);

    // 2) Q,K,V projections
    dim3 gE(E_ / 128, M_ / 128);
    sgemm_kernel<0><<<gE, 256>>>(h, Wq, bq, nullptr, q, M_, E_, E_);
    sgemm_kernel<0><<<gE, 256>>>(h, Wk, bk, nullptr, k, M_, E_, E_);
    sgemm_kernel<0><<<gE, 256>>>(h, Wv, bv, nullptr, v, M_, E_, E_);

    // 3) causal attention
    dim3 gA(T_ / 64, B_ * H_);
    attn_kernel<<<gA, 256, ATTN_SMEM>>>(q, k, v, attn);

    // 4) output projection + residual -> out = x + attn@Wp + bp
    sgemm_kernel<2><<<gE, 256>>>(attn, Wp, bp, x, out, M_, E_, E_);

    // 5) ln2
    ln_kernel<<<M_, 256>>>(out, ln2_g, ln2_b, h2);

    // 6) FFN1: relu(h2@W1 + b1)
    dim3 gF1(DFF_ / 128, M_ / 128);
    sgemm_kernel<1><<<gF1, 256>>>(h2, W1, b1, nullptr, ff, M_, DFF_, E_);

    // 7) FFN2 + residual (in-place on out): out = out + ff@W2 + b2
    dim3 gF2(E_ / 128, M_ / 128);
    sgemm_kernel<2><<<gF2, 256>>>(ff, W2, b2, out, out, M_, E_, DFF_);
}

// round 3
// speedup vs baseline: 2.2143x; 2.2143x over previous
#include <cuda_runtime.h>
#include <cuda_bf16.h>
#include <cstdint>

// Problem constants
#define B_   4
#define T_   2048
#define E_   1024
#define H_   16
#define HS_  64
#define DFF_ 4096
#define M_   (B_ * T_)   // 8192 rows

// ---------------------------------------------------------------------------
// Scratch (device globals)
// ---------------------------------------------------------------------------
__device__ float g_q[(size_t)M_ * E_];
__device__ float g_k[(size_t)M_ * E_];
__device__ float g_v[(size_t)M_ * E_];
// split-bf16 activations (reused: ln1-out -> attn-out -> ln2-out)
__device__ __nv_bfloat16 g_ah[(size_t)M_ * E_];
__device__ __nv_bfloat16 g_al[(size_t)M_ * E_];
// split-bf16 FFN hidden
__device__ __nv_bfloat16 g_fh[(size_t)M_ * DFF_];
__device__ __nv_bfloat16 g_fl[(size_t)M_ * DFF_];
// split-bf16 transposed weights [N,K]
__device__ __nv_bfloat16 g_wqh[(size_t)E_ * E_],  g_wql[(size_t)E_ * E_];
__device__ __nv_bfloat16 g_wkh[(size_t)E_ * E_],  g_wkl[(size_t)E_ * E_];
__device__ __nv_bfloat16 g_wvh[(size_t)E_ * E_],  g_wvl[(size_t)E_ * E_];
__device__ __nv_bfloat16 g_wph[(size_t)E_ * E_],  g_wpl[(size_t)E_ * E_];
__device__ __nv_bfloat16 g_w1h[(size_t)E_ * DFF_], g_w1l[(size_t)E_ * DFF_];
__device__ __nv_bfloat16 g_w2h[(size_t)DFF_ * E_], g_w2l[(size_t)DFF_ * E_];

// ---------------------------------------------------------------------------
// Helpers
// ---------------------------------------------------------------------------
__device__ __forceinline__ uint32_t smem_u32(const void* p) {
    uint32_t a;
    asm("{ .reg .u64 t; cvta.to.shared.u64 t, %1; cvt.u32.u64 %0, t; }"
        : "=r"(a) : "l"(p));
    return a;
}

__device__ __forceinline__ void ldm_x4(uint32_t* r, uint32_t addr) {
    asm volatile("ldmatrix.sync.aligned.m8n8.x4.shared.b16 {%0,%1,%2,%3}, [%4];"
                 : "=r"(r[0]), "=r"(r[1]), "=r"(r[2]), "=r"(r[3]) : "r"(addr));
}
__device__ __forceinline__ void ldm_x2(uint32_t* r, uint32_t addr) {
    asm volatile("ldmatrix.sync.aligned.m8n8.x2.shared.b16 {%0,%1}, [%2];"
                 : "=r"(r[0]), "=r"(r[1]) : "r"(addr));
}

__device__ __forceinline__ void mma16816(float* c, const uint32_t* a, const uint32_t* b) {
    asm volatile(
        "mma.sync.aligned.m16n8k16.row.col.f32.bf16.bf16.f32 "
        "{%0,%1,%2,%3}, {%4,%5,%6,%7}, {%8,%9}, {%0,%1,%2,%3};"
        : "+f"(c[0]), "+f"(c[1]), "+f"(c[2]), "+f"(c[3])
        : "r"(a[0]), "r"(a[1]), "r"(a[2]), "r"(a[3]), "r"(b[0]), "r"(b[1]));
}

#define CP_ASYNC16(dst, src) \
    asm volatile("cp.async.cg.shared.global [%0], [%1], 16;" :: "r"(dst), "l"(src))
#define CP_COMMIT() asm volatile("cp.async.commit_group;" ::: "memory")

// fp32 -> (bf16 hi, bf16 lo) pair, packed two-at-a-time
__device__ __forceinline__ void split_pair(float a, float b, uint32_t& hi, uint32_t& lo) {
    __nv_bfloat162 h = __floats2bfloat162_rn(a, b);
    float ra = a - __bfloat162float(h.x);
    float rb = b - __bfloat162float(h.y);
    __nv_bfloat162 l = __floats2bfloat162_rn(ra, rb);
    hi = *reinterpret_cast<uint32_t*>(&h);
    lo = *reinterpret_cast<uint32_t*>(&l);
}

// ---------------------------------------------------------------------------
// LayerNorm -> split bf16 output
// ---------------------------------------------------------------------------
__global__ __launch_bounds__(256)
void ln_split_kernel(const float* __restrict__ in, const float* __restrict__ gamma,
                     const float* __restrict__ beta,
                     __nv_bfloat16* __restrict__ Oh, __nv_bfloat16* __restrict__ Ol) {
    int row = blockIdx.x;
    int t = threadIdx.x;
    float4 v = ((const float4*)(in + (size_t)row * E_))[t];

    float s1 = v.x + v.y + v.z + v.w;
    float s2 = v.x * v.x + v.y * v.y + v.z * v.z + v.w * v.w;
    #pragma unroll
    for (int o = 16; o > 0; o >>= 1) {
        s1 += __shfl_xor_sync(0xffffffffu, s1, o);
        s2 += __shfl_xor_sync(0xffffffffu, s2, o);
    }
    __shared__ float red[64];
    int lane = t & 31, w = t >> 5;
    if (lane == 0) { red[w] = s1; red[w + 32] = s2; }
    __syncthreads();
    float ts1 = 0.f, ts2 = 0.f;
    #pragma unroll
    for (int i = 0; i < 8; i++) { ts1 += red[i]; ts2 += red[i + 32]; }

    float mu  = ts1 * (1.0f / E_);
    float var = ts2 * (1.0f / E_) - mu * mu;
    float rs  = rsqrtf(var + 1e-5f);

    float4 g4 = ((const float4*)gamma)[t];
    float4 b4 = ((const float4*)beta)[t];
    float o0 = (v.x - mu) * rs * g4.x + b4.x;
    float o1 = (v.y - mu) * rs * g4.y + b4.y;
    float o2 = (v.z - mu) * rs * g4.z + b4.z;
    float o3 = (v.w - mu) * rs * g4.w + b4.w;

    uint32_t h01, l01, h23, l23;
    split_pair(o0, o1, h01, l01);
    split_pair(o2, o3, h23, l23);
    size_t idx = (size_t)row * E_ + t * 4;
    *reinterpret_cast<uint2*>(Oh + idx) = make_uint2(h01, h23);
    *reinterpret_cast<uint2*>(Ol + idx) = make_uint2(l01, l23);
}

// ---------------------------------------------------------------------------
// Weight transpose + split: W[K,N] fp32 -> Th/Tl [N,K] bf16
// ---------------------------------------------------------------------------
__global__ void wtrans_kernel(const float* __restrict__ W,
                              __nv_bfloat16* __restrict__ Th,
                              __nv_bfloat16* __restrict__ Tl, int K, int N) {
    __shared__ float t[32][33];
    int n0 = blockIdx.x * 32, k0 = blockIdx.y * 32;
    int tx = threadIdx.x, ty = threadIdx.y;
    #pragma unroll
    for (int i = 0; i < 32; i += 8)
        t[ty + i][tx] = W[(size_t)(k0 + ty + i) * N + n0 + tx];
    __syncthreads();
    #pragma unroll
    for (int i = 0; i < 32; i += 8) {
        float v = t[tx][ty + i];
        __nv_bfloat16 h = __float2bfloat16(v);
        __nv_bfloat16 l = __float2bfloat16(v - __bfloat162float(h));
        size_t o = (size_t)(n0 + ty + i) * K + k0 + tx;
        Th[o] = h; Tl[o] = l;
    }
}

// ---------------------------------------------------------------------------
// mma.sync split-bf16 GEMM: C[M,N] = A[M,K] @ Wt[N,K]^T + bias (+relu/+res)
// 128x128 CTA tile, BK=64, 8 warps (2x4), warp tile 64x32, 2-stage cp.async.
// SW128 swizzled smem (128B bf16 rows) -> conflict-free ldmatrix.
// EPI: 0 = bias -> fp32 ; 1 = bias+relu -> split bf16 ; 2 = bias+res -> fp32
// ---------------------------------------------------------------------------
#define TILE_B   16384                      // 128 rows x 128 bytes
#define STAGE_B  (4 * TILE_B)               // Ah, Al, Bh, Bl
#define GSMEM    (2 * STAGE_B + 256)

__device__ __forceinline__ void cpa_tile(const __nv_bfloat16* __restrict__ g,
                                         int ldk, int k0, uint32_t sbase) {
    int tid = threadIdx.x;
    #pragma unroll
    for (int i = 0; i < 4; i++) {
        int idx = i * 256 + tid;
        int r = idx >> 3, c = idx & 7;
        uint32_t off = (uint32_t)(r * 128 + c * 16);
        off ^= (off >> 3) & 0x70;
        CP_ASYNC16(sbase + off, g + (size_t)r * ldk + k0 + c * 8);
    }
}

template<int EPI>
__global__ __launch_bounds__(256, 1)
void tgemm_kernel(const __nv_bfloat16* __restrict__ Ah, const __nv_bfloat16* __restrict__ Al,
                  const __nv_bfloat16* __restrict__ Bh, const __nv_bfloat16* __restrict__ Bl,
                  const float* __restrict__ bias, const float* __restrict__ res,
                  float* __restrict__ Cf,
                  __nv_bfloat16* __restrict__ Ch, __nv_bfloat16* __restrict__ Cl,
                  int M, int N, int K) {
    extern __shared__ char dsm[];
    uint32_t base = smem_u32(dsm);
    base = (base + 127) & ~127u;

    int tid = threadIdx.x, lane = tid & 31, wid = tid >> 5;
    int warp_m = wid >> 2;          // 0..1
    int warp_n = wid & 3;           // 0..3
    int m0 = blockIdx.y * 128, n0 = blockIdx.x * 128;

    const __nv_bfloat16* Ahb = Ah + (size_t)m0 * K;
    const __nv_bfloat16* Alb = Al + (size_t)m0 * K;
    const __nv_bfloat16* Bhb = Bh + (size_t)n0 * K;
    const __nv_bfloat16* Blb = Bl + (size_t)n0 * K;

    // ldmatrix lane geometry
    int amat = lane >> 3, arin = lane & 7;
    int aRow = warp_m * 64 + (amat & 1) * 8 + arin;   // + mi*16
    int aChk = amat >> 1;                              // + ks*2
    int bRow = warp_n * 32 + (lane & 7);               // + ni*8
    int bChk = (lane >> 3) & 1;                        // + ks*2

    float C[4][4][4];
    #pragma unroll
    for (int i = 0; i < 4; i++)
        #pragma unroll
        for (int j = 0; j < 4; j++)
            #pragma unroll
            for (int r = 0; r < 4; r++) C[i][j][r] = 0.f;

    int NT = K >> 6;

    // prologue: stage 0
    {
        uint32_t s0 = base;
        cpa_tile(Ahb, K, 0, s0 + 0 * TILE_B);
        cpa_tile(Alb, K, 0, s0 + 1 * TILE_B);
        cpa_tile(Bhb, K, 0, s0 + 2 * TILE_B);
        cpa_tile(Blb, K, 0, s0 + 3 * TILE_B);
        CP_COMMIT();
    }

    for (int kt = 0; kt < NT; kt++) {
        if (kt + 1 < NT) {
            uint32_t sn = base + ((kt + 1) & 1) * STAGE_B;
            int k0 = (kt + 1) << 6;
            cpa_tile(Ahb, K, k0, sn + 0 * TILE_B);
            cpa_tile(Alb, K, k0, sn + 1 * TILE_B);
            cpa_tile(Bhb, K, k0, sn + 2 * TILE_B);
            cpa_tile(Blb, K, k0, sn + 3 * TILE_B);
            CP_COMMIT();
            asm volatile("cp.async.wait_group 1;" ::: "memory");
        } else {
            asm volatile("cp.async.wait_group 0;" ::: "memory");
        }
        __syncthreads();

        uint32_t sc = base + (kt & 1) * STAGE_B;
        uint32_t sAh = sc, sAl = sc + TILE_B, sBh = sc + 2 * TILE_B, sBl = sc + 3 * TILE_B;

        #pragma unroll
        for (int ks = 0; ks < 4; ks++) {
            uint32_t ah[4][4], al[4][4], bh[4][2], bl[4][2];
            #pragma unroll
            for (int mi = 0; mi < 4; mi++) {
                uint32_t off = (uint32_t)((aRow + mi * 16) * 128 + (aChk + ks * 2) * 16);
                off ^= (off >> 3) & 0x70;
                ldm_x4(ah[mi], sAh + off);
                ldm_x4(al[mi], sAl + off);
            }
            #pragma unroll
            for (int ni = 0; ni < 4; ni++) {
                uint32_t off = (uint32_t)((bRow + ni * 8) * 128 + (bChk + ks * 2) * 16);
                off ^= (off >> 3) & 0x70;
                ldm_x2(bh[ni], sBh + off);
                ldm_x2(bl[ni], sBl + off);
            }
            #pragma unroll
            for (int mi = 0; mi < 4; mi++)
                #pragma unroll
                for (int ni = 0; ni < 4; ni++)
                    mma16816(C[mi][ni], ah[mi], bh[ni]);
            #pragma unroll
            for (int mi = 0; mi < 4; mi++)
                #pragma unroll
                for (int ni = 0; ni < 4; ni++)
                    mma16816(C[mi][ni], ah[mi], bl[ni]);
            #pragma unroll
            for (int mi = 0; mi < 4; mi++)
                #pragma unroll
                for (int ni = 0; ni < 4; ni++)
                    mma16816(C[mi][ni], al[mi], bh[ni]);
        }
        __syncthreads();
    }

    // Epilogue straight from C fragments
    int gq = lane >> 2, tig = lane & 3;
    #pragma unroll
    for (int mi = 0; mi < 4; mi++) {
        #pragma unroll
        for (int ni = 0; ni < 4; ni++) {
            int m = m0 + warp_m * 64 + mi * 16 + gq;
            int n = n0 + warp_n * 32 + ni * 8 + tig * 2;
            float2 bv = *reinterpret_cast<const float2*>(&bias[n]);
            #pragma unroll
            for (int half = 0; half < 2; half++) {
                int row = m + half * 8;
                float a0 = C[mi][ni][half * 2 + 0] + bv.x;
                float a1 = C[mi][ni][half * 2 + 1] + bv.y;
                size_t o = (size_t)row * N + n;
                if (EPI == 1) {
                    a0 = fmaxf(a0, 0.f); a1 = fmaxf(a1, 0.f);
                    uint32_t h01, l01;
                    split_pair(a0, a1, h01, l01);
                    *reinterpret_cast<uint32_t*>(Ch + o) = h01;
                    *reinterpret_cast<uint32_t*>(Cl + o) = l01;
                } else {
                    if (EPI == 2) {
                        float2 rv = *reinterpret_cast<const float2*>(&res[o]);
                        a0 += rv.x; a1 += rv.y;
                    }
                    *reinterpret_cast<float2*>(&Cf[o]) = make_float2(a0, a1);
                }
            }
        }
    }
}

// ---------------------------------------------------------------------------
// Causal flash attention, fp32 compute, split-bf16 output
// ---------------------------------------------------------------------------
#define ASTRIDE 68
#define ATTN_SMEM (4 * 64 * ASTRIDE * (int)sizeof(float))

__global__ __launch_bounds__(256)
void attn_kernel(const float* __restrict__ Q, const float* __restrict__ Kg,
                 const float* __restrict__ Vg,
                 __nv_bfloat16* __restrict__ Oh, __nv_bfloat16* __restrict__ Ol) {
    extern __shared__ float sm[];
    float* Qt = sm;
    float* Kt = sm + 64 * ASTRIDE;
    float* Vs = sm + 2 * 64 * ASTRIDE;
    float* Pt = sm + 3 * 64 * ASTRIDE;

    int tid = threadIdx.x;
    int q0 = blockIdx.x * 64;
    int bh = blockIdx.y;
    int b = bh >> 4, h = bh & 15;
    const float scale = 0.125f;

    size_t base = ((size_t)b * T_) * E_ + (size_t)h * HS_;

    for (int e = tid; e < 64 * 16; e += 256) {
        int r = e >> 4, d4 = (e & 15) * 4;
        float4 v = *(const float4*)(Q + base + (size_t)(q0 + r) * E_ + d4);
        Qt[(d4 + 0) * ASTRIDE + r] = v.x * scale;
        Qt[(d4 + 1) * ASTRIDE + r] = v.y * scale;
        Qt[(d4 + 2) * ASTRIDE + r] = v.z * scale;
        Qt[(d4 + 3) * ASTRIDE + r] = v.w * scale;
    }

    int tx = tid & 15, ty = tid >> 4;
    int r0 = ty * 4, c0 = tx * 4;

    float Oc[4][4] = {};
    float mrow[4] = {-1e30f, -1e30f, -1e30f, -1e30f};
    float lrow[4] = {};

    int ntiles = (q0 >> 6) + 1;
    for (int jt = 0; jt < ntiles; jt++) {
        int k0 = jt * 64;
        __syncthreads();
        for (int e = tid; e < 64 * 16; e += 256) {
            int r = e >> 4, d4 = (e & 15) * 4;
            float4 kv = *(const float4*)(Kg + base + (size_t)(k0 + r) * E_ + d4);
            Kt[(d4 + 0) * ASTRIDE + r] = kv.x;
            Kt[(d4 + 1) * ASTRIDE + r] = kv.y;
            Kt[(d4 + 2) * ASTRIDE + r] = kv.z;
            Kt[(d4 + 3) * ASTRIDE + r] = kv.w;
            float4 vv = *(const float4*)(Vg + base + (size_t)(k0 + r) * E_ + d4);
            *(float4*)&Vs[r * ASTRIDE + d4] = vv;
        }
        __syncthreads();

        float Sc[4][4] = {};
        #pragma unroll 8
        for (int d = 0; d < 64; d++) {
            float4 qv = *(const float4*)&Qt[d * ASTRIDE + r0];
            float4 kv = *(const float4*)&Kt[d * ASTRIDE + c0];
            float qa[4] = {qv.x, qv.y, qv.z, qv.w};
            float ka[4] = {kv.x, kv.y, kv.z, kv.w};
            #pragma unroll
            for (int i = 0; i < 4; i++)
                #pragma unroll
                for (int j = 0; j < 4; j++)
                    Sc[i][j] += qa[i] * ka[j];
        }

        if (jt == ntiles - 1) {
            #pragma unroll
            for (int i = 0; i < 4; i++)
                #pragma unroll
                for (int j = 0; j < 4; j++)
                    if (c0 + j > r0 + i) Sc[i][j] = -1e30f;
        }

        float mnew[4], al[4];
        #pragma unroll
        for (int i = 0; i < 4; i++) {
            float mx = fmaxf(fmaxf(Sc[i][0], Sc[i][1]), fmaxf(Sc[i][2], Sc[i][3]));
            #pragma unroll
            for (int o = 8; o > 0; o >>= 1)
                mx = fmaxf(mx, __shfl_xor_sync(0xffffffffu, mx, o));
            mnew[i] = fmaxf(mrow[i], mx);
            al[i] = __expf(mrow[i] - mnew[i]);
            mrow[i] = mnew[i];
        }
        #pragma unroll
        for (int i = 0; i < 4; i++) {
            float s = 0.f;
            #pragma unroll
            for (int j = 0; j < 4; j++) {
                Sc[i][j] = __expf(Sc[i][j] - mnew[i]);
                s += Sc[i][j];
            }
            #pragma unroll
            for (int o = 8; o > 0; o >>= 1)
                s += __shfl_xor_sync(0xffffffffu, s, o);
            lrow[i] = lrow[i] * al[i] + s;
            #pragma unroll
            for (int j = 0; j < 4; j++) Oc[i][j] *= al[i];
        }

        #pragma unroll
        for (int i = 0; i < 4; i++)
            #pragma unroll
            for (int j = 0; j < 4; j++)
                Pt[(c0 + j) * ASTRIDE + (r0 + i)] = Sc[i][j];
        __syncthreads();

        #pragma unroll 8
        for (int c = 0; c < 64; c++) {
            float4 pv = *(const float4*)&Pt[c * ASTRIDE + r0];
            float4 vv = *(const float4*)&Vs[c * ASTRIDE + c0];
            float pa[4] = {pv.x, pv.y, pv.z, pv.w};
            float va[4] = {vv.x, vv.y, vv.z, vv.w};
            #pragma unroll
            for (int i = 0; i < 4; i++)
                #pragma unroll
                for (int j = 0; j < 4; j++)
                    Oc[i][j] += pa[i] * va[j];
        }
    }

    #pragma unroll
    for (int i = 0; i < 4; i++) {
        float inv = 1.0f / lrow[i];
        float o0 = Oc[i][0] * inv, o1 = Oc[i][1] * inv;
        float o2 = Oc[i][2] * inv, o3 = Oc[i][3] * inv;
        uint32_t h01, l01, h23, l23;
        split_pair(o0, o1, h01, l01);
        split_pair(o2, o3, h23, l23);
        size_t idx = base + (size_t)(q0 + r0 + i) * E_ + c0;
        *reinterpret_cast<uint2*>(Oh + idx) = make_uint2(h01, h23);
        *reinterpret_cast<uint2*>(Ol + idx) = make_uint2(l01, l23);
    }
}

// ---------------------------------------------------------------------------
// Launch
// ---------------------------------------------------------------------------
extern "C" void kernel_launch(void* const* d_in, const int* in_sizes, int n_in,
                              void* d_out, int out_size) {
    (void)in_sizes; (void)n_in; (void)out_size;
    const float* x     = (const float*)d_in[0];
    const float* ln1_g = (const float*)d_in[1];
    const float* ln1_b = (const float*)d_in[2];
    const float* Wq    = (const float*)d_in[3];
    const float* bq    = (const float*)d_in[4];
    const float* Wk    = (const float*)d_in[5];
    const float* bk    = (const float*)d_in[6];
    const float* Wv    = (const float*)d_in[7];
    const float* bv    = (const float*)d_in[8];
    const float* Wp    = (const float*)d_in[9];
    const float* bp    = (const float*)d_in[10];
    const float* ln2_g = (const float*)d_in[11];
    const float* ln2_b = (const float*)d_in[12];
    const float* W1    = (const float*)d_in[13];
    const float* b1    = (const float*)d_in[14];
    const float* W2    = (const float*)d_in[15];
    const float* b2    = (const float*)d_in[16];
    float* out = (float*)d_out;

    float *q, *k, *v;
    __nv_bfloat16 *ah, *al, *fh, *fl;
    __nv_bfloat16 *wqh, *wql, *wkh, *wkl, *wvh, *wvl, *wph, *wpl, *w1h, *w1l, *w2h, *w2l;
    cudaGetSymbolAddress((void**)&q, g_q);
    cudaGetSymbolAddress((void**)&k, g_k);
    cudaGetSymbolAddress((void**)&v, g_v);
    cudaGetSymbolAddress((void**)&ah, g_ah);
    cudaGetSymbolAddress((void**)&al, g_al);
    cudaGetSymbolAddress((void**)&fh, g_fh);
    cudaGetSymbolAddress((void**)&fl, g_fl);
    cudaGetSymbolAddress((void**)&wqh, g_wqh);
    cudaGetSymbolAddress((void**)&wql, g_wql);
    cudaGetSymbolAddress((void**)&wkh, g_wkh);
    cudaGetSymbolAddress((void**)&wkl, g_wkl);
    cudaGetSymbolAddress((void**)&wvh, g_wvh);
    cudaGetSymbolAddress((void**)&wvl, g_wvl);
    cudaGetSymbolAddress((void**)&wph, g_wph);
    cudaGetSymbolAddress((void**)&wpl, g_wpl);
    cudaGetSymbolAddress((void**)&w1h, g_w1h);
    cudaGetSymbolAddress((void**)&w1l, g_w1l);
    cudaGetSymbolAddress((void**)&w2h, g_w2h);
    cudaGetSymbolAddress((void**)&w2l, g_w2l);

    cudaFuncSetAttribute(attn_kernel,
                         cudaFuncAttributeMaxDynamicSharedMemorySize, ATTN_SMEM);
    cudaFuncSetAttribute(tgemm_kernel<0>,
                         cudaFuncAttributeMaxDynamicSharedMemorySize, GSMEM);
    cudaFuncSetAttribute(tgemm_kernel<1>,
                         cudaFuncAttributeMaxDynamicSharedMemorySize, GSMEM);
    cudaFuncSetAttribute(tgemm_kernel<2>,
                         cudaFuncAttributeMaxDynamicSharedMemorySize, GSMEM);

    // weight transpose + split
    dim3 tb(32, 8);
    wtrans_kernel<<<dim3(E_ / 32, E_ / 32), tb>>>(Wq, wqh, wql, E_, E_);
    wtrans_kernel<<<dim3(E_ / 32, E_ / 32), tb>>>(Wk, wkh, wkl, E_, E_);
    wtrans_kernel<<<dim3(E_ / 32, E_ / 32), tb>>>(Wv, wvh, wvl, E_, E_);
    wtrans_kernel<<<dim3(E_ / 32, E_ / 32), tb>>>(Wp, wph, wpl, E_, E_);
    wtrans_kernel<<<dim3(DFF_ / 32, E_ / 32), tb>>>(W1, w1h, w1l, E_, DFF_);
    wtrans_kernel<<<dim3(E_ / 32, DFF_ / 32), tb>>>(W2, w2h, w2l, DFF_, E_);

    // ln1 -> split
    ln_split_kernel<<<M_, 256>>>(x, ln1_g, ln1_b, ah, al);

    // QKV
    dim3 gE(E_ / 128, M_ / 128);
    tgemm_kernel<0><<<gE, 256, GSMEM>>>(ah, al, wqh, wql, bq, nullptr, q,
                                        nullptr, nullptr, M_, E_, E_);
    tgemm_kernel<0><<<gE, 256, GSMEM>>>(ah, al, wkh, wkl, bk, nullptr, k,
                                        nullptr, nullptr, M_, E_, E_);
    tgemm_kernel<0><<<gE, 256, GSMEM>>>(ah, al, wvh, wvl, bv, nullptr, v,
                                        nullptr, nullptr, M_, E_, E_);

    // attention (writes split output into ah/al)
    dim3 gA(T_ / 64, B_ * H_);
    attn_kernel<<<gA, 256, ATTN_SMEM>>>(q, k, v, ah, al);

    // proj + residual
    tgemm_kernel<2><<<gE, 256, GSMEM>>>(ah, al, wph, wpl, bp, x, out,
                                        nullptr, nullptr, M_, E_, E_);

    // ln2 -> split
    ln_split_kernel<<<M_, 256>>>(out, ln2_g, ln2_b, ah, al);

    // FFN1 (relu, split output)
    dim3 gF1(DFF_ / 128, M_ / 128);
    tgemm_kernel<1><<<gF1, 256, GSMEM>>>(ah, al, w1h, w1l, b1, nullptr, nullptr,
                                         fh, fl, M_, DFF_, E_);

    // FFN2 + residual (in place on out)
    tgemm_kernel<2><<<gE, 256, GSMEM>>>(fh, fl, w2h, w2l, b2, out, out,
                                        nullptr, nullptr, M_, E_, DFF_);
}

// round 4
// speedup vs baseline: 3.2204x; 1.4543x over previous
#include <cuda_runtime.h>
#include <cuda_bf16.h>
#include <cstdint>

// Problem constants
#define B_   4
#define T_   2048
#define E_   1024
#define H_   16
#define HS_  64
#define DFF_ 4096
#define M_   (B_ * T_)   // 8192 rows

typedef __nv_bfloat16 bf16;

// ---------------------------------------------------------------------------
// Scratch (device globals)
// ---------------------------------------------------------------------------
// split-bf16 activations (reused: ln1-out -> attn-out -> ln2-out)
__device__ bf16 g_ah[(size_t)M_ * E_];
__device__ bf16 g_al[(size_t)M_ * E_];
// split-bf16 Q,K,V
__device__ bf16 g_qh[(size_t)M_ * E_], g_ql[(size_t)M_ * E_];
__device__ bf16 g_kh[(size_t)M_ * E_], g_kl[(size_t)M_ * E_];
__device__ bf16 g_vh[(size_t)M_ * E_], g_vl[(size_t)M_ * E_];
// split-bf16 FFN hidden
__device__ bf16 g_fh[(size_t)M_ * DFF_];
__device__ bf16 g_fl[(size_t)M_ * DFF_];
// split-bf16 transposed weights [N,K]
__device__ bf16 g_wqh[(size_t)E_ * E_],  g_wql[(size_t)E_ * E_];
__device__ bf16 g_wkh[(size_t)E_ * E_],  g_wkl[(size_t)E_ * E_];
__device__ bf16 g_wvh[(size_t)E_ * E_],  g_wvl[(size_t)E_ * E_];
__device__ bf16 g_wph[(size_t)E_ * E_],  g_wpl[(size_t)E_ * E_];
__device__ bf16 g_w1h[(size_t)E_ * DFF_], g_w1l[(size_t)E_ * DFF_];
__device__ bf16 g_w2h[(size_t)DFF_ * E_], g_w2l[(size_t)DFF_ * E_];

// ---------------------------------------------------------------------------
// Helpers
// ---------------------------------------------------------------------------
__device__ __forceinline__ uint32_t smem_u32(const void* p) {
    uint32_t a;
    asm("{ .reg .u64 t; cvta.to.shared.u64 t, %1; cvt.u32.u64 %0, t; }"
        : "=r"(a) : "l"(p));
    return a;
}

__device__ __forceinline__ void ldm_x4(uint32_t* r, uint32_t addr) {
    asm volatile("ldmatrix.sync.aligned.m8n8.x4.shared.b16 {%0,%1,%2,%3}, [%4];"
                 : "=r"(r[0]), "=r"(r[1]), "=r"(r[2]), "=r"(r[3]) : "r"(addr));
}
__device__ __forceinline__ void ldm_x4_t(uint32_t* r, uint32_t addr) {
    asm volatile("ldmatrix.sync.aligned.m8n8.x4.trans.shared.b16 {%0,%1,%2,%3}, [%4];"
                 : "=r"(r[0]), "=r"(r[1]), "=r"(r[2]), "=r"(r[3]) : "r"(addr));
}
__device__ __forceinline__ void ldm_x2(uint32_t* r, uint32_t addr) {
    asm volatile("ldmatrix.sync.aligned.m8n8.x2.shared.b16 {%0,%1}, [%2];"
                 : "=r"(r[0]), "=r"(r[1]) : "r"(addr));
}

__device__ __forceinline__ void mma16816(float* c, const uint32_t* a, const uint32_t* b) {
    asm volatile(
        "mma.sync.aligned.m16n8k16.row.col.f32.bf16.bf16.f32 "
        "{%0,%1,%2,%3}, {%4,%5,%6,%7}, {%8,%9}, {%0,%1,%2,%3};"
        : "+f"(c[0]), "+f"(c[1]), "+f"(c[2]), "+f"(c[3])
        : "r"(a[0]), "r"(a[1]), "r"(a[2]), "r"(a[3]), "r"(b[0]), "r"(b[1]));
}

#define CP_ASYNC16(dst, src) \
    asm volatile("cp.async.cg.shared.global [%0], [%1], 16;" :: "r"(dst), "l"(src))
#define CP_COMMIT() asm volatile("cp.async.commit_group;" ::: "memory")
#define CP_WAIT0() asm volatile("cp.async.wait_group 0;" ::: "memory")
#define CP_WAIT1() asm volatile("cp.async.wait_group 1;" ::: "memory")
#define CP_WAIT2() asm volatile("cp.async.wait_group 2;" ::: "memory")

// fp32 -> (bf16 hi, bf16 lo) pair, packed two-at-a-time
__device__ __forceinline__ void split_pair(float a, float b, uint32_t& hi, uint32_t& lo) {
    __nv_bfloat162 h = __floats2bfloat162_rn(a, b);
    float ra = a - __bfloat162float(h.x);
    float rb = b - __bfloat162float(h.y);
    __nv_bfloat162 l = __floats2bfloat162_rn(ra, rb);
    hi = *reinterpret_cast<uint32_t*>(&h);
    lo = *reinterpret_cast<uint32_t*>(&l);
}

// ---------------------------------------------------------------------------
// LayerNorm -> split bf16 output
// ---------------------------------------------------------------------------
__global__ __launch_bounds__(256)
void ln_split_kernel(const float* __restrict__ in, const float* __restrict__ gamma,
                     const float* __restrict__ beta,
                     bf16* __restrict__ Oh, bf16* __restrict__ Ol) {
    int row = blockIdx.x;
    int t = threadIdx.x;
    float4 v = ((const float4*)(in + (size_t)row * E_))[t];

    float s1 = v.x + v.y + v.z + v.w;
    float s2 = v.x * v.x + v.y * v.y + v.z * v.z + v.w * v.w;
    #pragma unroll
    for (int o = 16; o > 0; o >>= 1) {
        s1 += __shfl_xor_sync(0xffffffffu, s1, o);
        s2 += __shfl_xor_sync(0xffffffffu, s2, o);
    }
    __shared__ float red[64];
    int lane = t & 31, w = t >> 5;
    if (lane == 0) { red[w] = s1; red[w + 32] = s2; }
    __syncthreads();
    float ts1 = 0.f, ts2 = 0.f;
    #pragma unroll
    for (int i = 0; i < 8; i++) { ts1 += red[i]; ts2 += red[i + 32]; }

    float mu  = ts1 * (1.0f / E_);
    float var = ts2 * (1.0f / E_) - mu * mu;
    float rs  = rsqrtf(var + 1e-5f);

    float4 g4 = ((const float4*)gamma)[t];
    float4 b4 = ((const float4*)beta)[t];
    float o0 = (v.x - mu) * rs * g4.x + b4.x;
    float o1 = (v.y - mu) * rs * g4.y + b4.y;
    float o2 = (v.z - mu) * rs * g4.z + b4.z;
    float o3 = (v.w - mu) * rs * g4.w + b4.w;

    uint32_t h01, l01, h23, l23;
    split_pair(o0, o1, h01, l01);
    split_pair(o2, o3, h23, l23);
    size_t idx = (size_t)row * E_ + t * 4;
    *reinterpret_cast<uint2*>(Oh + idx) = make_uint2(h01, h23);
    *reinterpret_cast<uint2*>(Ol + idx) = make_uint2(l01, l23);
}

// ---------------------------------------------------------------------------
// Weight transpose + split: W[K,N] fp32 -> Th/Tl [N,K] bf16
// ---------------------------------------------------------------------------
__global__ void wtrans_kernel(const float* __restrict__ W,
                              bf16* __restrict__ Th,
                              bf16* __restrict__ Tl, int K, int N) {
    __shared__ float t[32][33];
    int n0 = blockIdx.x * 32, k0 = blockIdx.y * 32;
    int tx = threadIdx.x, ty = threadIdx.y;
    #pragma unroll
    for (int i = 0; i < 32; i += 8)
        t[ty + i][tx] = W[(size_t)(k0 + ty + i) * N + n0 + tx];
    __syncthreads();
    #pragma unroll
    for (int i = 0; i < 32; i += 8) {
        float v = t[tx][ty + i];
        bf16 h = __float2bfloat16(v);
        bf16 l = __float2bfloat16(v - __bfloat162float(h));
        size_t o = (size_t)(n0 + ty + i) * K + k0 + tx;
        Th[o] = h; Tl[o] = l;
    }
}

// ---------------------------------------------------------------------------
// GEMM core: C[M,N] = A[M,K] @ Wt[N,K]^T + bias (+relu/+res)
// 128x128 CTA tile, BK=64, 8 warps (2x4), 3-stage cp.async, SW128 smem.
// EPI: 1 = bias+relu -> split bf16 ; 2 = bias+res -> fp32 ; 3 = bias -> split bf16
// ---------------------------------------------------------------------------
#define TILE_B   16384                      // 128 rows x 128 bytes
#define STAGE_B  (4 * TILE_B)               // Ah, Al, Bh, Bl
#define GSMEM    (3 * STAGE_B + 256)

__device__ __forceinline__ void cpa_tile128(const bf16* __restrict__ g,
                                            int ldk, int k0, uint32_t sbase) {
    int tid = threadIdx.x;
    #pragma unroll
    for (int i = 0; i < 4; i++) {
        int idx = i * 256 + tid;
        int r = idx >> 3, c = idx & 7;
        uint32_t off = (uint32_t)(r * 128 + c * 16);
        off ^= (off >> 3) & 0x70;
        CP_ASYNC16(sbase + off, g + (size_t)r * ldk + k0 + c * 8);
    }
}

template<int EPI>
__device__ __forceinline__ void gemm_core(
        const bf16* __restrict__ Ah, const bf16* __restrict__ Al,
        const bf16* __restrict__ Bh, const bf16* __restrict__ Bl,
        const float* __restrict__ bias, const float* __restrict__ res,
        float* __restrict__ Cf, bf16* __restrict__ Ch, bf16* __restrict__ Cl,
        int M, int N, int K, int m0, int n0, uint32_t base) {
    int tid = threadIdx.x, lane = tid & 31, wid = tid >> 5;
    int warp_m = wid >> 2;          // 0..1
    int warp_n = wid & 3;           // 0..3

    const bf16* Ahb = Ah + (size_t)m0 * K;
    const bf16* Alb = Al + (size_t)m0 * K;
    const bf16* Bhb = Bh + (size_t)n0 * K;
    const bf16* Blb = Bl + (size_t)n0 * K;

    int amat = lane >> 3, arin = lane & 7;
    int aRow = warp_m * 64 + (amat & 1) * 8 + arin;
    int aChk = amat >> 1;
    int bRow = warp_n * 32 + (lane & 7);
    int bChk = (lane >> 3) & 1;

    float C[4][4][4];
    #pragma unroll
    for (int i = 0; i < 4; i++)
        #pragma unroll
        for (int j = 0; j < 4; j++)
            #pragma unroll
            for (int r = 0; r < 4; r++) C[i][j][r] = 0.f;

    int NT = K >> 6;

    // prologue: stages 0,1
    {
        cpa_tile128(Ahb, K, 0, base + 0 * TILE_B);
        cpa_tile128(Alb, K, 0, base + 1 * TILE_B);
        cpa_tile128(Bhb, K, 0, base + 2 * TILE_B);
        cpa_tile128(Blb, K, 0, base + 3 * TILE_B);
        CP_COMMIT();
        if (NT > 1) {
            uint32_t s1 = base + STAGE_B;
            cpa_tile128(Ahb, K, 64, s1 + 0 * TILE_B);
            cpa_tile128(Alb, K, 64, s1 + 1 * TILE_B);
            cpa_tile128(Bhb, K, 64, s1 + 2 * TILE_B);
            cpa_tile128(Blb, K, 64, s1 + 3 * TILE_B);
            CP_COMMIT();
        }
    }

    for (int kt = 0; kt < NT; kt++) {
        if (kt + 2 < NT) {
            int st = (kt + 2) % 3;
            uint32_t sn = base + st * STAGE_B;
            int k0 = (kt + 2) << 6;
            cpa_tile128(Ahb, K, k0, sn + 0 * TILE_B);
            cpa_tile128(Alb, K, k0, sn + 1 * TILE_B);
            cpa_tile128(Bhb, K, k0, sn + 2 * TILE_B);
            cpa_tile128(Blb, K, k0, sn + 3 * TILE_B);
            CP_COMMIT();
            CP_WAIT2();
        } else if (kt + 1 < NT) {
            CP_WAIT1();
        } else {
            CP_WAIT0();
        }
        __syncthreads();

        uint32_t sc = base + (kt % 3) * STAGE_B;
        uint32_t sAh = sc, sAl = sc + TILE_B, sBh = sc + 2 * TILE_B, sBl = sc + 3 * TILE_B;

        #pragma unroll
        for (int ks = 0; ks < 4; ks++) {
            uint32_t ah[4][4], al[4][4], bh[4][2], bl[4][2];
            #pragma unroll
            for (int mi = 0; mi < 4; mi++) {
                uint32_t off = (uint32_t)((aRow + mi * 16) * 128 + (aChk + ks * 2) * 16);
                off ^= (off >> 3) & 0x70;
                ldm_x4(ah[mi], sAh + off);
                ldm_x4(al[mi], sAl + off);
            }
            #pragma unroll
            for (int ni = 0; ni < 4; ni++) {
                uint32_t off = (uint32_t)((bRow + ni * 8) * 128 + (bChk + ks * 2) * 16);
                off ^= (off >> 3) & 0x70;
                ldm_x2(bh[ni], sBh + off);
                ldm_x2(bl[ni], sBl + off);
            }
            #pragma unroll
            for (int mi = 0; mi < 4; mi++)
                #pragma unroll
                for (int ni = 0; ni < 4; ni++)
                    mma16816(C[mi][ni], ah[mi], bh[ni]);
            #pragma unroll
            for (int mi = 0; mi < 4; mi++)
                #pragma unroll
                for (int ni = 0; ni < 4; ni++)
                    mma16816(C[mi][ni], ah[mi], bl[ni]);
            #pragma unroll
            for (int mi = 0; mi < 4; mi++)
                #pragma unroll
                for (int ni = 0; ni < 4; ni++)
                    mma16816(C[mi][ni], al[mi], bh[ni]);
        }
        __syncthreads();
    }

    // Epilogue straight from C fragments
    int gq = lane >> 2, tig = lane & 3;
    #pragma unroll
    for (int mi = 0; mi < 4; mi++) {
        #pragma unroll
        for (int ni = 0; ni < 4; ni++) {
            int m = m0 + warp_m * 64 + mi * 16 + gq;
            int n = n0 + warp_n * 32 + ni * 8 + tig * 2;
            float2 bv = *reinterpret_cast<const float2*>(&bias[n]);
            #pragma unroll
            for (int half = 0; half < 2; half++) {
                int row = m + half * 8;
                float a0 = C[mi][ni][half * 2 + 0] + bv.x;
                float a1 = C[mi][ni][half * 2 + 1] + bv.y;
                size_t o = (size_t)row * N + n;
                if (EPI == 1 || EPI == 3) {
                    if (EPI == 1) { a0 = fmaxf(a0, 0.f); a1 = fmaxf(a1, 0.f); }
                    uint32_t h01, l01;
                    split_pair(a0, a1, h01, l01);
                    *reinterpret_cast<uint32_t*>(Ch + o) = h01;
                    *reinterpret_cast<uint32_t*>(Cl + o) = l01;
                } else {
                    float2 rv = *reinterpret_cast<const float2*>(&res[o]);
                    a0 += rv.x; a1 += rv.y;
                    *reinterpret_cast<float2*>(&Cf[o]) = make_float2(a0, a1);
                }
            }
        }
    }
}

template<int EPI>
__global__ __launch_bounds__(256, 1)
void tgemm_kernel(const bf16* __restrict__ Ah, const bf16* __restrict__ Al,
                  const bf16* __restrict__ Bh, const bf16* __restrict__ Bl,
                  const float* __restrict__ bias, const float* __restrict__ res,
                  float* __restrict__ Cf, bf16* __restrict__ Ch, bf16* __restrict__ Cl,
                  int M, int N, int K) {
    extern __shared__ char dsm[];
    uint32_t base = smem_u32(dsm);
    base = (base + 127) & ~127u;
    gemm_core<EPI>(Ah, Al, Bh, Bl, bias, res, Cf, Ch, Cl, M, N, K,
                   blockIdx.y * 128, blockIdx.x * 128, base);
}

// Fused QKV: grid.z selects which projection
struct QKVArgs {
    const bf16* wh[3];
    const bf16* wl[3];
    const float* bias[3];
    bf16* oh[3];
    bf16* ol[3];
};

__global__ __launch_bounds__(256, 1)
void qkv_kernel(const bf16* __restrict__ Ah, const bf16* __restrict__ Al,
                QKVArgs args) {
    extern __shared__ char dsm[];
    uint32_t base = smem_u32(dsm);
    base = (base + 127) & ~127u;
    int z = blockIdx.z;
    gemm_core<3>(Ah, Al, args.wh[z], args.wl[z], args.bias[z], nullptr,
                 nullptr, args.oh[z], args.ol[z], M_, E_, E_,
                 blockIdx.y * 128, blockIdx.x * 128, base);
}

// ---------------------------------------------------------------------------
// Tensor-core causal flash attention: split-bf16 QK^T and PV, fp32 softmax.
// CTA = 128 threads (4 warps), 64 q-rows per CTA, k-tiles of 64, 2-stage.
// smem: Qh/Ql (16KB) + 2 stages x (Kh,Kl,Vh,Vl: 32KB) = 80KB
// ---------------------------------------------------------------------------
#define AQ_OFF   0
#define AST_OFF  16384
#define AST_SZ   32768
#define ATTN_SMEM (16384 + 2 * AST_SZ + 256)
#define CEXP 0.18033688011112042f   // 0.125 * log2(e)

__device__ __forceinline__ void cpa_tile64(const bf16* __restrict__ g,
                                           uint32_t sbase) {
    int tid = threadIdx.x;   // 128 threads
    #pragma unroll
    for (int i = 0; i < 4; i++) {
        int idx = i * 128 + tid;
        int r = idx >> 3, c = idx & 7;
        uint32_t off = (uint32_t)(r * 128 + c * 16);
        off ^= (off >> 3) & 0x70;
        CP_ASYNC16(sbase + off, g + (size_t)r * E_ + c * 8);
    }
}

__global__ __launch_bounds__(128, 2)
void attn_mma_kernel(const bf16* __restrict__ Qh, const bf16* __restrict__ Ql,
                     const bf16* __restrict__ Kh, const bf16* __restrict__ Kl,
                     const bf16* __restrict__ Vh, const bf16* __restrict__ Vl,
                     bf16* __restrict__ Oh, bf16* __restrict__ Ol) {
    extern __shared__ char dsm[];
    uint32_t base = smem_u32(dsm);
    base = (base + 127) & ~127u;

    int tid = threadIdx.x, lane = tid & 31, w = tid >> 5;
    int gq = lane >> 2, tig = lane & 3;
    int q0 = blockIdx.x * 64;
    int bh = blockIdx.y;
    int b = bh >> 4, h = bh & 15;
    size_t gbase = ((size_t)b * T_) * E_ + (size_t)h * HS_;

    // Q tiles -> smem
    cpa_tile64(Qh + gbase + (size_t)q0 * E_, base + AQ_OFF);
    cpa_tile64(Ql + gbase + (size_t)q0 * E_, base + AQ_OFF + 8192);
    CP_COMMIT();
    // K/V tile 0 -> stage 0
    {
        uint32_t s0 = base + AST_OFF;
        cpa_tile64(Kh + gbase, s0 + 0);
        cpa_tile64(Kl + gbase, s0 + 8192);
        cpa_tile64(Vh + gbase, s0 + 16384);
        cpa_tile64(Vl + gbase, s0 + 24576);
        CP_COMMIT();
    }
    CP_WAIT1();        // Q ready
    __syncthreads();

    // Q A-fragments (registers, reused across all k-tiles)
    uint32_t qfh[4][4], qfl[4][4];
    {
        int arow = w * 16 + (lane & 7) + ((lane & 8) ? 8 : 0);
        int asel = (lane >> 4) & 1;
        #pragma unroll
        for (int ks = 0; ks < 4; ks++) {
            uint32_t off = (uint32_t)(arow * 128 + (ks * 2 + asel) * 16);
            off ^= (off >> 3) & 0x70;
            ldm_x4(qfh[ks], base + AQ_OFF + off);
            ldm_x4(qfl[ks], base + AQ_OFF + 8192 + off);
        }
    }

    float O[8][4];
    #pragma unroll
    for (int s = 0; s < 8; s++)
        #pragma unroll
        for (int r = 0; r < 4; r++) O[s][r] = 0.f;
    float m0r = -1e30f, m1r = -1e30f, l0r = 0.f, l1r = 0.f;

    // lane geometry for K (B-frag, non-trans) and V (B-frag, trans)
    int kRowBase = (lane & 7) + ((lane >= 16) ? 8 : 0);   // + g*16
    int kChkSel  = (lane & 8) ? 1 : 0;                    // + ks*2
    int vRowBase = (lane & 7) + ((lane & 8) ? 8 : 0);     // + kk*16
    int vColB    = ((lane >= 16) ? 16 : 0);               // + g*32 (bytes)

    int nt = (q0 >> 6) + 1;
    for (int jt = 0; jt < nt; jt++) {
        if (jt + 1 < nt) {
            uint32_t sn = base + AST_OFF + ((jt + 1) & 1) * AST_SZ;
            size_t koff = gbase + (size_t)((jt + 1) * 64) * E_;
            cpa_tile64(Kh + koff, sn + 0);
            cpa_tile64(Kl + koff, sn + 8192);
            cpa_tile64(Vh + koff, sn + 16384);
            cpa_tile64(Vl + koff, sn + 24576);
            CP_COMMIT();
            CP_WAIT1();
        } else {
            CP_WAIT0();
        }
        __syncthreads();

        uint32_t sc  = base + AST_OFF + (jt & 1) * AST_SZ;
        uint32_t sKh = sc, sKl = sc + 8192, sVh = sc + 16384, sVl = sc + 24576;

        // ---- S = Q K^T (3-term split) ----
        float S[8][4];
        #pragma unroll
        for (int s = 0; s < 8; s++)
            #pragma unroll
            for (int r = 0; r < 4; r++) S[s][r] = 0.f;

        #pragma unroll
        for (int ks = 0; ks < 4; ks++) {
            #pragma unroll
            for (int g = 0; g < 4; g++) {
                uint32_t kh4[4], kl4[4];
                uint32_t off = (uint32_t)((g * 16 + kRowBase) * 128 +
                                          (ks * 2 + kChkSel) * 16);
                off ^= (off >> 3) & 0x70;
                ldm_x4(kh4, sKh + off);
                ldm_x4(kl4, sKl + off);
                mma16816(S[2 * g],     qfh[ks], &kh4[0]);
                mma16816(S[2 * g],     qfh[ks], &kl4[0]);
                mma16816(S[2 * g],     qfl[ks], &kh4[0]);
                mma16816(S[2 * g + 1], qfh[ks], &kh4[2]);
                mma16816(S[2 * g + 1], qfh[ks], &kl4[2]);
                mma16816(S[2 * g + 1], qfl[ks], &kh4[2]);
            }
        }

        // ---- causal mask (diagonal tile only) ----
        if (jt == nt - 1) {
            int qr0 = q0 + w * 16 + gq;
            int kc0 = jt * 64 + 2 * tig;
            #pragma unroll
            for (int s = 0; s < 8; s++) {
                int kc = kc0 + s * 8;
                if (kc     > qr0)     S[s][0] = -1e30f;
                if (kc + 1 > qr0)     S[s][1] = -1e30f;
                if (kc     > qr0 + 8) S[s][2] = -1e30f;
                if (kc + 1 > qr0 + 8) S[s][3] = -1e30f;
            }
        }

        // ---- online softmax ----
        float mx0 = -1e30f, mx1 = -1e30f;
        #pragma unroll
        for (int s = 0; s < 8; s++) {
            mx0 = fmaxf(mx0, fmaxf(S[s][0], S[s][1]));
            mx1 = fmaxf(mx1, fmaxf(S[s][2], S[s][3]));
        }
        mx0 = fmaxf(mx0, __shfl_xor_sync(0xffffffffu, mx0, 1));
        mx0 = fmaxf(mx0, __shfl_xor_sync(0xffffffffu, mx0, 2));
        mx1 = fmaxf(mx1, __shfl_xor_sync(0xffffffffu, mx1, 1));
        mx1 = fmaxf(mx1, __shfl_xor_sync(0xffffffffu, mx1, 2));

        float mn0 = fmaxf(m0r, mx0), mn1 = fmaxf(m1r, mx1);
        float al0 = exp2f((m0r - mn0) * CEXP);
        float al1 = exp2f((m1r - mn1) * CEXP);
        m0r = mn0; m1r = mn1;

        float ls0 = 0.f, ls1 = 0.f;
        #pragma unroll
        for (int s = 0; s < 8; s++) {
            S[s][0] = exp2f((S[s][0] - mn0) * CEXP);
            S[s][1] = exp2f((S[s][1] - mn0) * CEXP);
            S[s][2] = exp2f((S[s][2] - mn1) * CEXP);
            S[s][3] = exp2f((S[s][3] - mn1) * CEXP);
            ls0 += S[s][0] + S[s][1];
            ls1 += S[s][2] + S[s][3];
        }
        ls0 += __shfl_xor_sync(0xffffffffu, ls0, 1);
        ls0 += __shfl_xor_sync(0xffffffffu, ls0, 2);
        ls1 += __shfl_xor_sync(0xffffffffu, ls1, 1);
        ls1 += __shfl_xor_sync(0xffffffffu, ls1, 2);
        l0r = l0r * al0 + ls0;
        l1r = l1r * al1 + ls1;

        #pragma unroll
        for (int s = 0; s < 8; s++) {
            O[s][0] *= al0; O[s][1] *= al0;
            O[s][2] *= al1; O[s][3] *= al1;
        }

        // ---- split P into A-fragments (no shuffles needed) ----
        uint32_t pah[4][4], pal[4][4];
        #pragma unroll
        for (int kk = 0; kk < 4; kk++) {
            split_pair(S[2 * kk][0],     S[2 * kk][1],     pah[kk][0], pal[kk][0]);
            split_pair(S[2 * kk][2],     S[2 * kk][3],     pah[kk][1], pal[kk][1]);
            split_pair(S[2 * kk + 1][0], S[2 * kk + 1][1], pah[kk][2], pal[kk][2]);
            split_pair(S[2 * kk + 1][2], S[2 * kk + 1][3], pah[kk][3], pal[kk][3]);
        }

        // ---- O += P V (3-term split) ----
        #pragma unroll
        for (int kk = 0; kk < 4; kk++) {
            #pragma unroll
            for (int g = 0; g < 4; g++) {
                uint32_t vh4[4], vl4[4];
                uint32_t off = (uint32_t)((kk * 16 + vRowBase) * 128 +
                                          g * 32 + vColB);
                off ^= (off >> 3) & 0x70;
                ldm_x4_t(vh4, sVh + off);
                ldm_x4_t(vl4, sVl + off);
                mma16816(O[2 * g],     pah[kk], &vh4[0]);
                mma16816(O[2 * g],     pah[kk], &vl4[0]);
                mma16816(O[2 * g],     pal[kk], &vh4[0]);
                mma16816(O[2 * g + 1], pah[kk], &vh4[2]);
                mma16816(O[2 * g + 1], pah[kk], &vl4[2]);
                mma16816(O[2 * g + 1], pal[kk], &vh4[2]);
            }
        }
        __syncthreads();   // compute done before next iter overwrites stage
    }

    // ---- normalize + split-store ----
    float inv0 = 1.0f / l0r, inv1 = 1.0f / l1r;
    int row0 = q0 + w * 16 + gq;
    #pragma unroll
    for (int s = 0; s < 8; s++) {
        int col = s * 8 + 2 * tig;
        uint32_t h01, l01;
        split_pair(O[s][0] * inv0, O[s][1] * inv0, h01, l01);
        size_t o0 = gbase + (size_t)row0 * E_ + col;
        *reinterpret_cast<uint32_t*>(Oh + o0) = h01;
        *reinterpret_cast<uint32_t*>(Ol + o0) = l01;
        split_pair(O[s][2] * inv1, O[s][3] * inv1, h01, l01);
        size_t o1 = gbase + (size_t)(row0 + 8) * E_ + col;
        *reinterpret_cast<uint32_t*>(Oh + o1) = h01;
        *reinterpret_cast<uint32_t*>(Ol + o1) = l01;
    }
}

// ---------------------------------------------------------------------------
// Launch
// ---------------------------------------------------------------------------
extern "C" void kernel_launch(void* const* d_in, const int* in_sizes, int n_in,
                              void* d_out, int out_size) {
    (void)in_sizes; (void)n_in; (void)out_size;
    const float* x     = (const float*)d_in[0];
    const float* ln1_g = (const float*)d_in[1];
    const float* ln1_b = (const float*)d_in[2];
    const float* Wq    = (const float*)d_in[3];
    const float* bq    = (const float*)d_in[4];
    const float* Wk    = (const float*)d_in[5];
    const float* bk    = (const float*)d_in[6];
    const float* Wv    = (const float*)d_in[7];
    const float* bv    = (const float*)d_in[8];
    const float* Wp    = (const float*)d_in[9];
    const float* bp    = (const float*)d_in[10];
    const float* ln2_g = (const float*)d_in[11];
    const float* ln2_b = (const float*)d_in[12];
    const float* W1    = (const float*)d_in[13];
    const float* b1    = (const float*)d_in[14];
    const float* W2    = (const float*)d_in[15];
    const float* b2    = (const float*)d_in[16];
    float* out = (float*)d_out;

    bf16 *ah, *al, *fh, *fl, *qh, *ql, *kh, *kl, *vh, *vl;
    bf16 *wqh, *wql, *wkh, *wkl, *wvh, *wvl, *wph, *wpl, *w1h, *w1l, *w2h, *w2l;
    cudaGetSymbolAddress((void**)&ah, g_ah);
    cudaGetSymbolAddress((void**)&al, g_al);
    cudaGetSymbolAddress((void**)&fh, g_fh);
    cudaGetSymbolAddress((void**)&fl, g_fl);
    cudaGetSymbolAddress((void**)&qh, g_qh);
    cudaGetSymbolAddress((void**)&ql, g_ql);
    cudaGetSymbolAddress((void**)&kh, g_kh);
    cudaGetSymbolAddress((void**)&kl, g_kl);
    cudaGetSymbolAddress((void**)&vh, g_vh);
    cudaGetSymbolAddress((void**)&vl, g_vl);
    cudaGetSymbolAddress((void**)&wqh, g_wqh);
    cudaGetSymbolAddress((void**)&wql, g_wql);
    cudaGetSymbolAddress((void**)&wkh, g_wkh);
    cudaGetSymbolAddress((void**)&wkl, g_wkl);
    cudaGetSymbolAddress((void**)&wvh, g_wvh);
    cudaGetSymbolAddress((void**)&wvl, g_wvl);
    cudaGetSymbolAddress((void**)&wph, g_wph);
    cudaGetSymbolAddress((void**)&wpl, g_wpl);
    cudaGetSymbolAddress((void**)&w1h, g_w1h);
    cudaGetSymbolAddress((void**)&w1l, g_w1l);
    cudaGetSymbolAddress((void**)&w2h, g_w2h);
    cudaGetSymbolAddress((void**)&w2l, g_w2l);

    cudaFuncSetAttribute(attn_mma_kernel,
                         cudaFuncAttributeMaxDynamicSharedMemorySize, ATTN_SMEM);
    cudaFuncSetAttribute(tgemm_kernel<1>,
                         cudaFuncAttributeMaxDynamicSharedMemorySize, GSMEM);
    cudaFuncSetAttribute(tgemm_kernel<2>,
                         cudaFuncAttributeMaxDynamicSharedMemorySize, GSMEM);
    cudaFuncSetAttribute(qkv_kernel,
                         cudaFuncAttributeMaxDynamicSharedMemorySize, GSMEM);

    // weight transpose + split
    dim3 tb(32, 8);
    wtrans_kernel<<<dim3(E_ / 32, E_ / 32), tb>>>(Wq, wqh, wql, E_, E_);
    wtrans_kernel<<<dim3(E_ / 32, E_ / 32), tb>>>(Wk, wkh, wkl, E_, E_);
    wtrans_kernel<<<dim3(E_ / 32, E_ / 32), tb>>>(Wv, wvh, wvl, E_, E_);
    wtrans_kernel<<<dim3(E_ / 32, E_ / 32), tb>>>(Wp, wph, wpl, E_, E_);
    wtrans_kernel<<<dim3(DFF_ / 32, E_ / 32), tb>>>(W1, w1h, w1l, E_, DFF_);
    wtrans_kernel<<<dim3(E_ / 32, DFF_ / 32), tb>>>(W2, w2h, w2l, DFF_, E_);

    // ln1 -> split
    ln_split_kernel<<<M_, 256>>>(x, ln1_g, ln1_b, ah, al);

    // fused QKV (split-bf16 outputs)
    QKVArgs qa;
    qa.wh[0] = wqh; qa.wl[0] = wql; qa.bias[0] = bq; qa.oh[0] = qh; qa.ol[0] = ql;
    qa.wh[1] = wkh; qa.wl[1] = wkl; qa.bias[1] = bk; qa.oh[1] = kh; qa.ol[1] = kl;
    qa.wh[2] = wvh; qa.wl[2] = wvl; qa.bias[2] = bv; qa.oh[2] = vh; qa.ol[2] = vl;
    dim3 gQKV(E_ / 128, M_ / 128, 3);
    qkv_kernel<<<gQKV, 256, GSMEM>>>(ah, al, qa);

    // tensor-core attention (split output into ah/al)
    dim3 gA(T_ / 64, B_ * H_);
    attn_mma_kernel<<<gA, 128, ATTN_SMEM>>>(qh, ql, kh, kl, vh, vl, ah, al);

    // proj + residual
    dim3 gE(E_ / 128, M_ / 128);
    tgemm_kernel<2><<<gE, 256, GSMEM>>>(ah, al, wph, wpl, bp, x, out,
                                        nullptr, nullptr, M_, E_, E_);

    // ln2 -> split
    ln_split_kernel<<<M_, 256>>>(out, ln2_g, ln2_b, ah, al);

    // FFN1 (relu, split output)
    dim3 gF1(DFF_ / 128, M_ / 128);
    tgemm_kernel<1><<<gF1, 256, GSMEM>>>(ah, al, w1h, w1l, b1, nullptr, nullptr,
                                         fh, fl, M_, DFF_, E_);

    // FFN2 + residual (in place on out)
    tgemm_kernel<2><<<gE, 256, GSMEM>>>(fh, fl, w2h, w2l, b2, out, out,
                                        nullptr, nullptr, M_, E_, DFF_);
}

// round 5
// speedup vs baseline: 3.3529x; 1.0412x over previous
#include <cuda_runtime.h>
#include <cuda_bf16.h>
#include <cstdint>

// Problem constants
#define B_   4
#define T_   2048
#define E_   1024
#define H_   16
#define HS_  64
#define DFF_ 4096
#define M_   (B_ * T_)   // 8192 rows

typedef __nv_bfloat16 bf16;

// ---------------------------------------------------------------------------
// Scratch (device globals)
// ---------------------------------------------------------------------------
__device__ bf16 g_ah[(size_t)M_ * E_];
__device__ bf16 g_al[(size_t)M_ * E_];
__device__ bf16 g_qh[(size_t)M_ * E_], g_ql[(size_t)M_ * E_];
__device__ bf16 g_kh[(size_t)M_ * E_], g_kl[(size_t)M_ * E_];
__device__ bf16 g_vh[(size_t)M_ * E_], g_vl[(size_t)M_ * E_];
__device__ bf16 g_fh[(size_t)M_ * DFF_];
__device__ bf16 g_fl[(size_t)M_ * DFF_];
__device__ bf16 g_wqh[(size_t)E_ * E_],  g_wql[(size_t)E_ * E_];
__device__ bf16 g_wkh[(size_t)E_ * E_],  g_wkl[(size_t)E_ * E_];
__device__ bf16 g_wvh[(size_t)E_ * E_],  g_wvl[(size_t)E_ * E_];
__device__ bf16 g_wph[(size_t)E_ * E_],  g_wpl[(size_t)E_ * E_];
__device__ bf16 g_w1h[(size_t)E_ * DFF_], g_w1l[(size_t)E_ * DFF_];
__device__ bf16 g_w2h[(size_t)DFF_ * E_], g_w2l[(size_t)DFF_ * E_];

// ---------------------------------------------------------------------------
// Helpers
// ---------------------------------------------------------------------------
__device__ __forceinline__ uint32_t smem_u32(const void* p) {
    uint32_t a;
    asm("{ .reg .u64 t; cvta.to.shared.u64 t, %1; cvt.u32.u64 %0, t; }"
        : "=r"(a) : "l"(p));
    return a;
}

__device__ __forceinline__ void ldm_x4(uint32_t* r, uint32_t addr) {
    asm volatile("ldmatrix.sync.aligned.m8n8.x4.shared.b16 {%0,%1,%2,%3}, [%4];"
                 : "=r"(r[0]), "=r"(r[1]), "=r"(r[2]), "=r"(r[3]) : "r"(addr));
}
__device__ __forceinline__ void ldm_x4_t(uint32_t* r, uint32_t addr) {
    asm volatile("ldmatrix.sync.aligned.m8n8.x4.trans.shared.b16 {%0,%1,%2,%3}, [%4];"
                 : "=r"(r[0]), "=r"(r[1]), "=r"(r[2]), "=r"(r[3]) : "r"(addr));
}
__device__ __forceinline__ void ldm_x2(uint32_t* r, uint32_t addr) {
    asm volatile("ldmatrix.sync.aligned.m8n8.x2.shared.b16 {%0,%1}, [%2];"
                 : "=r"(r[0]), "=r"(r[1]) : "r"(addr));
}

__device__ __forceinline__ void mma16816(float* c, const uint32_t* a, const uint32_t* b) {
    asm volatile(
        "mma.sync.aligned.m16n8k16.row.col.f32.bf16.bf16.f32 "
        "{%0,%1,%2,%3}, {%4,%5,%6,%7}, {%8,%9}, {%0,%1,%2,%3};"
        : "+f"(c[0]), "+f"(c[1]), "+f"(c[2]), "+f"(c[3])
        : "r"(a[0]), "r"(a[1]), "r"(a[2]), "r"(a[3]), "r"(b[0]), "r"(b[1]));
}

#define CP_ASYNC16(dst, src) \
    asm volatile("cp.async.cg.shared.global [%0], [%1], 16;" :: "r"(dst), "l"(src))
#define CP_COMMIT() asm volatile("cp.async.commit_group;" ::: "memory")
#define CP_WAIT0() asm volatile("cp.async.wait_group 0;" ::: "memory")
#define CP_WAIT1() asm volatile("cp.async.wait_group 1;" ::: "memory")
#define CP_WAIT2() asm volatile("cp.async.wait_group 2;" ::: "memory")

__device__ __forceinline__ void split_pair(float a, float b, uint32_t& hi, uint32_t& lo) {
    __nv_bfloat162 h = __floats2bfloat162_rn(a, b);
    float ra = a - __bfloat162float(h.x);
    float rb = b - __bfloat162float(h.y);
    __nv_bfloat162 l = __floats2bfloat162_rn(ra, rb);
    hi = *reinterpret_cast<uint32_t*>(&h);
    lo = *reinterpret_cast<uint32_t*>(&l);
}

// ---------------------------------------------------------------------------
// LayerNorm -> split bf16 output
// ---------------------------------------------------------------------------
__global__ __launch_bounds__(256)
void ln_split_kernel(const float* __restrict__ in, const float* __restrict__ gamma,
                     const float* __restrict__ beta,
                     bf16* __restrict__ Oh, bf16* __restrict__ Ol) {
    int row = blockIdx.x;
    int t = threadIdx.x;
    float4 v = ((const float4*)(in + (size_t)row * E_))[t];

    float s1 = v.x + v.y + v.z + v.w;
    float s2 = v.x * v.x + v.y * v.y + v.z * v.z + v.w * v.w;
    #pragma unroll
    for (int o = 16; o > 0; o >>= 1) {
        s1 += __shfl_xor_sync(0xffffffffu, s1, o);
        s2 += __shfl_xor_sync(0xffffffffu, s2, o);
    }
    __shared__ float red[64];
    int lane = t & 31, w = t >> 5;
    if (lane == 0) { red[w] = s1; red[w + 32] = s2; }
    __syncthreads();
    float ts1 = 0.f, ts2 = 0.f;
    #pragma unroll
    for (int i = 0; i < 8; i++) { ts1 += red[i]; ts2 += red[i + 32]; }

    float mu  = ts1 * (1.0f / E_);
    float var = ts2 * (1.0f / E_) - mu * mu;
    float rs  = rsqrtf(var + 1e-5f);

    float4 g4 = ((const float4*)gamma)[t];
    float4 b4 = ((const float4*)beta)[t];
    float o0 = (v.x - mu) * rs * g4.x + b4.x;
    float o1 = (v.y - mu) * rs * g4.y + b4.y;
    float o2 = (v.z - mu) * rs * g4.z + b4.z;
    float o3 = (v.w - mu) * rs * g4.w + b4.w;

    uint32_t h01, l01, h23, l23;
    split_pair(o0, o1, h01, l01);
    split_pair(o2, o3, h23, l23);
    size_t idx = (size_t)row * E_ + t * 4;
    *reinterpret_cast<uint2*>(Oh + idx) = make_uint2(h01, h23);
    *reinterpret_cast<uint2*>(Ol + idx) = make_uint2(l01, l23);
}

// ---------------------------------------------------------------------------
// Weight transpose + split: W[K,N] fp32 -> Th/Tl [N,K] bf16
// ---------------------------------------------------------------------------
__global__ void wtrans_kernel(const float* __restrict__ W,
                              bf16* __restrict__ Th,
                              bf16* __restrict__ Tl, int K, int N) {
    __shared__ float t[32][33];
    int n0 = blockIdx.x * 32, k0 = blockIdx.y * 32;
    int tx = threadIdx.x, ty = threadIdx.y;
    #pragma unroll
    for (int i = 0; i < 32; i += 8)
        t[ty + i][tx] = W[(size_t)(k0 + ty + i) * N + n0 + tx];
    __syncthreads();
    #pragma unroll
    for (int i = 0; i < 32; i += 8) {
        float v = t[tx][ty + i];
        bf16 h = __float2bfloat16(v);
        bf16 l = __float2bfloat16(v - __bfloat162float(h));
        size_t o = (size_t)(n0 + ty + i) * K + k0 + tx;
        Th[o] = h; Tl[o] = l;
    }
}

// ---------------------------------------------------------------------------
// GEMM core: C[M,N] = A[M,K] @ Wt[N,K]^T + bias (+relu/+res)
// 128x128 CTA tile, BK=64, 8 warps (2x4), 3-stage cp.async, SW128 smem,
// ONE __syncthreads per k-iter (prefetch after compute).
// EPI: 1 = bias+relu -> split bf16 ; 2 = bias+res -> fp32 ; 3 = bias -> split bf16
// ---------------------------------------------------------------------------
#define TILE_B   16384
#define STAGE_B  (4 * TILE_B)
#define GSMEM    (3 * STAGE_B + 256)

__device__ __forceinline__ void cpa_tile128(const bf16* __restrict__ g,
                                            int ldk, int k0, uint32_t sbase) {
    int tid = threadIdx.x;
    #pragma unroll
    for (int i = 0; i < 4; i++) {
        int idx = i * 256 + tid;
        int r = idx >> 3, c = idx & 7;
        uint32_t off = (uint32_t)(r * 128 + c * 16);
        off ^= (off >> 3) & 0x70;
        CP_ASYNC16(sbase + off, g + (size_t)r * ldk + k0 + c * 8);
    }
}

template<int EPI>
__device__ __forceinline__ void gemm_core(
        const bf16* __restrict__ Ah, const bf16* __restrict__ Al,
        const bf16* __restrict__ Bh, const bf16* __restrict__ Bl,
        const float* __restrict__ bias, const float* __restrict__ res,
        float* __restrict__ Cf, bf16* __restrict__ Ch, bf16* __restrict__ Cl,
        int M, int N, int K, int m0, int n0, uint32_t base) {
    int tid = threadIdx.x, lane = tid & 31, wid = tid >> 5;
    int warp_m = wid >> 2;
    int warp_n = wid & 3;

    const bf16* Ahb = Ah + (size_t)m0 * K;
    const bf16* Alb = Al + (size_t)m0 * K;
    const bf16* Bhb = Bh + (size_t)n0 * K;
    const bf16* Blb = Bl + (size_t)n0 * K;

    int amat = lane >> 3, arin = lane & 7;
    int aRow = warp_m * 64 + (amat & 1) * 8 + arin;
    int aChk = amat >> 1;
    int bRow = warp_n * 32 + (lane & 7);
    int bChk = (lane >> 3) & 1;

    float C[4][4][4];
    #pragma unroll
    for (int i = 0; i < 4; i++)
        #pragma unroll
        for (int j = 0; j < 4; j++)
            #pragma unroll
            for (int r = 0; r < 4; r++) C[i][j][r] = 0.f;

    int NT = K >> 6;

    // prologue: stages 0,1 (one commit group per stage)
    cpa_tile128(Ahb, K, 0, base + 0 * TILE_B);
    cpa_tile128(Alb, K, 0, base + 1 * TILE_B);
    cpa_tile128(Bhb, K, 0, base + 2 * TILE_B);
    cpa_tile128(Blb, K, 0, base + 3 * TILE_B);
    CP_COMMIT();
    {
        uint32_t s1 = base + STAGE_B;
        cpa_tile128(Ahb, K, 64, s1 + 0 * TILE_B);
        cpa_tile128(Alb, K, 64, s1 + 1 * TILE_B);
        cpa_tile128(Bhb, K, 64, s1 + 2 * TILE_B);
        cpa_tile128(Blb, K, 64, s1 + 3 * TILE_B);
        CP_COMMIT();
    }

    for (int kt = 0; kt < NT; kt++) {
        if (kt + 1 < NT) { CP_WAIT1(); } else { CP_WAIT0(); }
        __syncthreads();

        uint32_t sc = base + (kt % 3) * STAGE_B;
        uint32_t sAh = sc, sAl = sc + TILE_B, sBh = sc + 2 * TILE_B, sBl = sc + 3 * TILE_B;

        #pragma unroll
        for (int ks = 0; ks < 4; ks++) {
            uint32_t ah[4][4], al[4][4], bh[4][2], bl[4][2];
            #pragma unroll
            for (int mi = 0; mi < 4; mi++) {
                uint32_t off = (uint32_t)((aRow + mi * 16) * 128 + (aChk + ks * 2) * 16);
                off ^= (off >> 3) & 0x70;
                ldm_x4(ah[mi], sAh + off);
                ldm_x4(al[mi], sAl + off);
            }
            #pragma unroll
            for (int ni = 0; ni < 4; ni++) {
                uint32_t off = (uint32_t)((bRow + ni * 8) * 128 + (bChk + ks * 2) * 16);
                off ^= (off >> 3) & 0x70;
                ldm_x2(bh[ni], sBh + off);
                ldm_x2(bl[ni], sBl + off);
            }
            #pragma unroll
            for (int mi = 0; mi < 4; mi++)
                #pragma unroll
                for (int ni = 0; ni < 4; ni++)
                    mma16816(C[mi][ni], ah[mi], bh[ni]);
            #pragma unroll
            for (int mi = 0; mi < 4; mi++)
                #pragma unroll
                for (int ni = 0; ni < 4; ni++)
                    mma16816(C[mi][ni], ah[mi], bl[ni]);
            #pragma unroll
            for (int mi = 0; mi < 4; mi++)
                #pragma unroll
                for (int ni = 0; ni < 4; ni++)
                    mma16816(C[mi][ni], al[mi], bh[ni]);
        }

        // prefetch kt+2 AFTER compute: writes stage (kt+2)%3 == (kt-1)%3,
        // last read at iter kt-1, protected by the sync at top of this iter.
        if (kt + 2 < NT) {
            uint32_t sn = base + ((kt + 2) % 3) * STAGE_B;
            int k0 = (kt + 2) << 6;
            cpa_tile128(Ahb, K, k0, sn + 0 * TILE_B);
            cpa_tile128(Alb, K, k0, sn + 1 * TILE_B);
            cpa_tile128(Bhb, K, k0, sn + 2 * TILE_B);
            cpa_tile128(Blb, K, k0, sn + 3 * TILE_B);
            CP_COMMIT();
        }
    }

    // Epilogue straight from C fragments
    int gq = lane >> 2, tig = lane & 3;
    #pragma unroll
    for (int mi = 0; mi < 4; mi++) {
        #pragma unroll
        for (int ni = 0; ni < 4; ni++) {
            int m = m0 + warp_m * 64 + mi * 16 + gq;
            int n = n0 + warp_n * 32 + ni * 8 + tig * 2;
            float2 bv = *reinterpret_cast<const float2*>(&bias[n]);
            #pragma unroll
            for (int half = 0; half < 2; half++) {
                int row = m + half * 8;
                float a0 = C[mi][ni][half * 2 + 0] + bv.x;
                float a1 = C[mi][ni][half * 2 + 1] + bv.y;
                size_t o = (size_t)row * N + n;
                if (EPI == 1 || EPI == 3) {
                    if (EPI == 1) { a0 = fmaxf(a0, 0.f); a1 = fmaxf(a1, 0.f); }
                    uint32_t h01, l01;
                    split_pair(a0, a1, h01, l01);
                    *reinterpret_cast<uint32_t*>(Ch + o) = h01;
                    *reinterpret_cast<uint32_t*>(Cl + o) = l01;
                } else {
                    float2 rv = *reinterpret_cast<const float2*>(&res[o]);
                    a0 += rv.x; a1 += rv.y;
                    *reinterpret_cast<float2*>(&Cf[o]) = make_float2(a0, a1);
                }
            }
        }
    }
}

template<int EPI>
__global__ __launch_bounds__(256, 1)
void tgemm_kernel(const bf16* __restrict__ Ah, const bf16* __restrict__ Al,
                  const bf16* __restrict__ Bh, const bf16* __restrict__ Bl,
                  const float* __restrict__ bias, const float* __restrict__ res,
                  float* __restrict__ Cf, bf16* __restrict__ Ch, bf16* __restrict__ Cl,
                  int M, int N, int K) {
    extern __shared__ char dsm[];
    uint32_t base = smem_u32(dsm);
    base = (base + 127) & ~127u;
    gemm_core<EPI>(Ah, Al, Bh, Bl, bias, res, Cf, Ch, Cl, M, N, K,
                   blockIdx.y * 128, blockIdx.x * 128, base);
}

struct QKVArgs {
    const bf16* wh[3];
    const bf16* wl[3];
    const float* bias[3];
    bf16* oh[3];
    bf16* ol[3];
};

__global__ __launch_bounds__(256, 1)
void qkv_kernel(const bf16* __restrict__ Ah, const bf16* __restrict__ Al,
                QKVArgs args) {
    extern __shared__ char dsm[];
    uint32_t base = smem_u32(dsm);
    base = (base + 127) & ~127u;
    int z = blockIdx.z;
    gemm_core<3>(Ah, Al, args.wh[z], args.wl[z], args.bias[z], nullptr,
                 nullptr, args.oh[z], args.ol[z], M_, E_, E_,
                 blockIdx.y * 128, blockIdx.x * 128, base);
}

// ---------------------------------------------------------------------------
// Tensor-core causal flash attention, q-tile 128, 8 warps, 3-stage KV pipe.
// smem: Qh/Ql 32KB + 3 x 32KB KV stages = 128KB. 1 CTA/SM.
// ---------------------------------------------------------------------------
#define AQ_BYTES  32768
#define AST_SZ    32768
#define ATTN_SMEM (AQ_BYTES + 3 * AST_SZ + 256)
#define CEXP 0.18033688011112042f   // 0.125 * log2(e)

__device__ __forceinline__ void cpa_tile64(const bf16* __restrict__ g,
                                           uint32_t sbase) {
    int tid = threadIdx.x;   // 256 threads
    #pragma unroll
    for (int i = 0; i < 2; i++) {
        int idx = i * 256 + tid;
        int r = idx >> 3, c = idx & 7;
        uint32_t off = (uint32_t)(r * 128 + c * 16);
        off ^= (off >> 3) & 0x70;
        CP_ASYNC16(sbase + off, g + (size_t)r * E_ + c * 8);
    }
}

__global__ __launch_bounds__(256, 1)
void attn_mma_kernel(const bf16* __restrict__ Qh, const bf16* __restrict__ Ql,
                     const bf16* __restrict__ Kh, const bf16* __restrict__ Kl,
                     const bf16* __restrict__ Vh, const bf16* __restrict__ Vl,
                     bf16* __restrict__ Oh, bf16* __restrict__ Ol) {
    extern __shared__ char dsm[];
    uint32_t base = smem_u32(dsm);
    base = (base + 127) & ~127u;

    int tid = threadIdx.x, lane = tid & 31, w = tid >> 5;
    int gq = lane >> 2, tig = lane & 3;
    // reversed order: largest-work tiles first
    int qi = gridDim.x - 1 - blockIdx.x;
    int q0 = qi * 128;
    int bh = blockIdx.y;
    int b = bh >> 4, h = bh & 15;
    size_t gbase = ((size_t)b * T_) * E_ + (size_t)h * HS_;

    int nt = (q0 >> 6) + 2;   // k-tiles of 64 covering [0, q0+128)

    // group 0: Q (hi+lo)
    cpa_tile128(Qh + gbase + (size_t)q0 * E_, E_, 0, base);
    cpa_tile128(Ql + gbase + (size_t)q0 * E_, E_, 0, base + 16384);
    CP_COMMIT();
    // groups 1,2: KV stages 0,1
    #pragma unroll
    for (int st = 0; st < 2; st++) {
        uint32_t s = base + AQ_BYTES + st * AST_SZ;
        size_t koff = gbase + (size_t)(st * 64) * E_;
        cpa_tile64(Kh + koff, s + 0);
        cpa_tile64(Kl + koff, s + 8192);
        cpa_tile64(Vh + koff, s + 16384);
        cpa_tile64(Vl + koff, s + 24576);
        CP_COMMIT();
    }

    CP_WAIT2();          // Q landed
    __syncthreads();

    // Q A-fragments (registers, reused across all k-tiles)
    uint32_t qfh[4][4], qfl[4][4];
    {
        int arow = w * 16 + (lane & 7) + ((lane & 8) ? 8 : 0);
        int asel = (lane >> 4) & 1;
        #pragma unroll
        for (int ks = 0; ks < 4; ks++) {
            uint32_t off = (uint32_t)(arow * 128 + (ks * 2 + asel) * 16);
            off ^= (off >> 3) & 0x70;
            ldm_x4(qfh[ks], base + off);
            ldm_x4(qfl[ks], base + 16384 + off);
        }
    }

    float O[8][4];
    #pragma unroll
    for (int s = 0; s < 8; s++)
        #pragma unroll
        for (int r = 0; r < 4; r++) O[s][r] = 0.f;
    float m0r = -1e30f, m1r = -1e30f, l0r = 0.f, l1r = 0.f;

    int kRowBase = (lane & 7) + ((lane >= 16) ? 8 : 0);
    int kChkSel  = (lane & 8) ? 1 : 0;
    int vRowBase = (lane & 7) + ((lane & 8) ? 8 : 0);
    int vColB    = ((lane >= 16) ? 16 : 0);

    int maskFrom = q0 >> 6;   // tiles jt >= this intersect the causal edge

    for (int jt = 0; jt < nt; jt++) {
        if (jt + 1 < nt) { CP_WAIT1(); } else { CP_WAIT0(); }
        __syncthreads();

        uint32_t sc  = base + AQ_BYTES + (jt % 3) * AST_SZ;
        uint32_t sKh = sc, sKl = sc + 8192, sVh = sc + 16384, sVl = sc + 24576;

        // ---- S = Q K^T (3-term split) ----
        float S[8][4];
        #pragma unroll
        for (int s = 0; s < 8; s++)
            #pragma unroll
            for (int r = 0; r < 4; r++) S[s][r] = 0.f;

        #pragma unroll
        for (int ks = 0; ks < 4; ks++) {
            #pragma unroll
            for (int g = 0; g < 4; g++) {
                uint32_t kh4[4], kl4[4];
                uint32_t off = (uint32_t)((g * 16 + kRowBase) * 128 +
                                          (ks * 2 + kChkSel) * 16);
                off ^= (off >> 3) & 0x70;
                ldm_x4(kh4, sKh + off);
                ldm_x4(kl4, sKl + off);
                mma16816(S[2 * g],     qfh[ks], &kh4[0]);
                mma16816(S[2 * g],     qfh[ks], &kl4[0]);
                mma16816(S[2 * g],     qfl[ks], &kh4[0]);
                mma16816(S[2 * g + 1], qfh[ks], &kh4[2]);
                mma16816(S[2 * g + 1], qfh[ks], &kl4[2]);
                mma16816(S[2 * g + 1], qfl[ks], &kh4[2]);
            }
        }

        // ---- causal mask on edge tiles ----
        if (jt >= maskFrom) {
            int qr0 = q0 + w * 16 + gq;
            int kc0 = jt * 64 + 2 * tig;
            #pragma unroll
            for (int s = 0; s < 8; s++) {
                int kc = kc0 + s * 8;
                if (kc     > qr0)     S[s][0] = -1e30f;
                if (kc + 1 > qr0)     S[s][1] = -1e30f;
                if (kc     > qr0 + 8) S[s][2] = -1e30f;
                if (kc + 1 > qr0 + 8) S[s][3] = -1e30f;
            }
        }

        // ---- online softmax ----
        float mx0 = -1e30f, mx1 = -1e30f;
        #pragma unroll
        for (int s = 0; s < 8; s++) {
            mx0 = fmaxf(mx0, fmaxf(S[s][0], S[s][1]));
            mx1 = fmaxf(mx1, fmaxf(S[s][2], S[s][3]));
        }
        mx0 = fmaxf(mx0, __shfl_xor_sync(0xffffffffu, mx0, 1));
        mx0 = fmaxf(mx0, __shfl_xor_sync(0xffffffffu, mx0, 2));
        mx1 = fmaxf(mx1, __shfl_xor_sync(0xffffffffu, mx1, 1));
        mx1 = fmaxf(mx1, __shfl_xor_sync(0xffffffffu, mx1, 2));

        float mn0 = fmaxf(m0r, mx0), mn1 = fmaxf(m1r, mx1);
        float al0 = exp2f((m0r - mn0) * CEXP);
        float al1 = exp2f((m1r - mn1) * CEXP);
        m0r = mn0; m1r = mn1;

        float ls0 = 0.f, ls1 = 0.f;
        #pragma unroll
        for (int s = 0; s < 8; s++) {
            S[s][0] = exp2f((S[s][0] - mn0) * CEXP);
            S[s][1] = exp2f((S[s][1] - mn0) * CEXP);
            S[s][2] = exp2f((S[s][2] - mn1) * CEXP);
            S[s][3] = exp2f((S[s][3] - mn1) * CEXP);
            ls0 += S[s][0] + S[s][1];
            ls1 += S[s][2] + S[s][3];
        }
        ls0 += __shfl_xor_sync(0xffffffffu, ls0, 1);
        ls0 += __shfl_xor_sync(0xffffffffu, ls0, 2);
        ls1 += __shfl_xor_sync(0xffffffffu, ls1, 1);
        ls1 += __shfl_xor_sync(0xffffffffu, ls1, 2);
        l0r = l0r * al0 + ls0;
        l1r = l1r * al1 + ls1;

        #pragma unroll
        for (int s = 0; s < 8; s++) {
            O[s][0] *= al0; O[s][1] *= al0;
            O[s][2] *= al1; O[s][3] *= al1;
        }

        // ---- split P into A-fragments ----
        uint32_t pah[4][4], pal[4][4];
        #pragma unroll
        for (int kk = 0; kk < 4; kk++) {
            split_pair(S[2 * kk][0],     S[2 * kk][1],     pah[kk][0], pal[kk][0]);
            split_pair(S[2 * kk][2],     S[2 * kk][3],     pah[kk][1], pal[kk][1]);
            split_pair(S[2 * kk + 1][0], S[2 * kk + 1][1], pah[kk][2], pal[kk][2]);
            split_pair(S[2 * kk + 1][2], S[2 * kk + 1][3], pah[kk][3], pal[kk][3]);
        }

        // ---- O += P V (3-term split) ----
        #pragma unroll
        for (int kk = 0; kk < 4; kk++) {
            #pragma unroll
            for (int g = 0; g < 4; g++) {
                uint32_t vh4[4], vl4[4];
                uint32_t off = (uint32_t)((kk * 16 + vRowBase) * 128 +
                                          g * 32 + vColB);
                off ^= (off >> 3) & 0x70;
                ldm_x4_t(vh4, sVh + off);
                ldm_x4_t(vl4, sVl + off);
                mma16816(O[2 * g],     pah[kk], &vh4[0]);
                mma16816(O[2 * g],     pah[kk], &vl4[0]);
                mma16816(O[2 * g],     pal[kk], &vh4[0]);
                mma16816(O[2 * g + 1], pah[kk], &vh4[2]);
                mma16816(O[2 * g + 1], pah[kk], &vl4[2]);
                mma16816(O[2 * g + 1], pal[kk], &vh4[2]);
            }
        }

        // prefetch KV tile jt+2 AFTER compute (stage (jt+2)%3, safe: last
        // read at jt-1, protected by sync at top of this iter)
        if (jt + 2 < nt) {
            uint32_t sn = base + AQ_BYTES + ((jt + 2) % 3) * AST_SZ;
            size_t koff = gbase + (size_t)((jt + 2) * 64) * E_;
            cpa_tile64(Kh + koff, sn + 0);
            cpa_tile64(Kl + koff, sn + 8192);
            cpa_tile64(Vh + koff, sn + 16384);
            cpa_tile64(Vl + koff, sn + 24576);
            CP_COMMIT();
        }
    }

    // ---- normalize + split-store ----
    float inv0 = 1.0f / l0r, inv1 = 1.0f / l1r;
    int row0 = q0 + w * 16 + gq;
    #pragma unroll
    for (int s = 0; s < 8; s++) {
        int col = s * 8 + 2 * tig;
        uint32_t h01, l01;
        split_pair(O[s][0] * inv0, O[s][1] * inv0, h01, l01);
        size_t o0 = gbase + (size_t)row0 * E_ + col;
        *reinterpret_cast<uint32_t*>(Oh + o0) = h01;
        *reinterpret_cast<uint32_t*>(Ol + o0) = l01;
        split_pair(O[s][2] * inv1, O[s][3] * inv1, h01, l01);
        size_t o1 = gbase + (size_t)(row0 + 8) * E_ + col;
        *reinterpret_cast<uint32_t*>(Oh + o1) = h01;
        *reinterpret_cast<uint32_t*>(Ol + o1) = l01;
    }
}

// ---------------------------------------------------------------------------
// Launch
// ---------------------------------------------------------------------------
extern "C" void kernel_launch(void* const* d_in, const int* in_sizes, int n_in,
                              void* d_out, int out_size) {
    (void)in_sizes; (void)n_in; (void)out_size;
    const float* x     = (const float*)d_in[0];
    const float* ln1_g = (const float*)d_in[1];
    const float* ln1_b = (const float*)d_in[2];
    const float* Wq    = (const float*)d_in[3];
    const float* bq    = (const float*)d_in[4];
    const float* Wk    = (const float*)d_in[5];
    const float* bk    = (const float*)d_in[6];
    const float* Wv    = (const float*)d_in[7];
    const float* bv    = (const float*)d_in[8];
    const float* Wp    = (const float*)d_in[9];
    const float* bp    = (const float*)d_in[10];
    const float* ln2_g = (const float*)d_in[11];
    const float* ln2_b = (const float*)d_in[12];
    const float* W1    = (const float*)d_in[13];
    const float* b1    = (const float*)d_in[14];
    const float* W2    = (const float*)d_in[15];
    const float* b2    = (const float*)d_in[16];
    float* out = (float*)d_out;

    bf16 *ah, *al, *fh, *fl, *qh, *ql, *kh, *kl, *vh, *vl;
    bf16 *wqh, *wql, *wkh, *wkl, *wvh, *wvl, *wph, *wpl, *w1h, *w1l, *w2h, *w2l;
    cudaGetSymbolAddress((void**)&ah, g_ah);
    cudaGetSymbolAddress((void**)&al, g_al);
    cudaGetSymbolAddress((void**)&fh, g_fh);
    cudaGetSymbolAddress((void**)&fl, g_fl);
    cudaGetSymbolAddress((void**)&qh, g_qh);
    cudaGetSymbolAddress((void**)&ql, g_ql);
    cudaGetSymbolAddress((void**)&kh, g_kh);
    cudaGetSymbolAddress((void**)&kl, g_kl);
    cudaGetSymbolAddress((void**)&vh, g_vh);
    cudaGetSymbolAddress((void**)&vl, g_vl);
    cudaGetSymbolAddress((void**)&wqh, g_wqh);
    cudaGetSymbolAddress((void**)&wql, g_wql);
    cudaGetSymbolAddress((void**)&wkh, g_wkh);
    cudaGetSymbolAddress((void**)&wkl, g_wkl);
    cudaGetSymbolAddress((void**)&wvh, g_wvh);
    cudaGetSymbolAddress((void**)&wvl, g_wvl);
    cudaGetSymbolAddress((void**)&wph, g_wph);
    cudaGetSymbolAddress((void**)&wpl, g_wpl);
    cudaGetSymbolAddress((void**)&w1h, g_w1h);
    cudaGetSymbolAddress((void**)&w1l, g_w1l);
    cudaGetSymbolAddress((void**)&w2h, g_w2h);
    cudaGetSymbolAddress((void**)&w2l, g_w2l);

    cudaFuncSetAttribute(attn_mma_kernel,
                         cudaFuncAttributeMaxDynamicSharedMemorySize, ATTN_SMEM);
    cudaFuncSetAttribute(tgemm_kernel<1>,
                         cudaFuncAttributeMaxDynamicSharedMemorySize, GSMEM);
    cudaFuncSetAttribute(tgemm_kernel<2>,
                         cudaFuncAttributeMaxDynamicSharedMemorySize, GSMEM);
    cudaFuncSetAttribute(qkv_kernel,
                         cudaFuncAttributeMaxDynamicSharedMemorySize, GSMEM);

    dim3 tb(32, 8);
    // launches 1-4: QKV+proj weight transposes (so launch #6 = qkv for ncu -s 5)
    wtrans_kernel<<<dim3(E_ / 32, E_ / 32), tb>>>(Wq, wqh, wql, E_, E_);
    wtrans_kernel<<<dim3(E_ / 32, E_ / 32), tb>>>(Wk, wkh, wkl, E_, E_);
    wtrans_kernel<<<dim3(E_ / 32, E_ / 32), tb>>>(Wv, wvh, wvl, E_, E_);
    wtrans_kernel<<<dim3(E_ / 32, E_ / 32), tb>>>(Wp, wph, wpl, E_, E_);

    // launch 5: ln1 -> split
    ln_split_kernel<<<M_, 256>>>(x, ln1_g, ln1_b, ah, al);

    // launch 6: fused QKV (ncu capture target)
    QKVArgs qa;
    qa.wh[0] = wqh; qa.wl[0] = wql; qa.bias[0] = bq; qa.oh[0] = qh; qa.ol[0] = ql;
    qa.wh[1] = wkh; qa.wl[1] = wkl; qa.bias[1] = bk; qa.oh[1] = kh; qa.ol[1] = kl;
    qa.wh[2] = wvh; qa.wl[2] = wvl; qa.bias[2] = bv; qa.oh[2] = vh; qa.ol[2] = vl;
    dim3 gQKV(E_ / 128, M_ / 128, 3);
    qkv_kernel<<<gQKV, 256, GSMEM>>>(ah, al, qa);

    // FFN weight transposes (independent; before their consumers)
    wtrans_kernel<<<dim3(DFF_ / 32, E_ / 32), tb>>>(W1, w1h, w1l, E_, DFF_);
    wtrans_kernel<<<dim3(E_ / 32, DFF_ / 32), tb>>>(W2, w2h, w2l, DFF_, E_);

    // tensor-core attention (split output into ah/al)
    dim3 gA(T_ / 128, B_ * H_);
    attn_mma_kernel<<<gA, 256, ATTN_SMEM>>>(qh, ql, kh, kl, vh, vl, ah, al);

    // proj + residual
    dim3 gE(E_ / 128, M_ / 128);
    tgemm_kernel<2><<<gE, 256, GSMEM>>>(ah, al, wph, wpl, bp, x, out,
                                        nullptr, nullptr, M_, E_, E_);

    // ln2 -> split
    ln_split_kernel<<<M_, 256>>>(out, ln2_g, ln2_b, ah, al);

    // FFN1 (relu, split output)
    dim3 gF1(DFF_ / 128, M_ / 128);
    tgemm_kernel<1><<<gF1, 256, GSMEM>>>(ah, al, w1h, w1l, b1, nullptr, nullptr,
                                         fh, fl, M_, DFF_, E_);

    // FFN2 + residual (in place on out)
    tgemm_kernel<2><<<gE, 256, GSMEM>>>(fh, fl, w2h, w2l, b2, out, out,
                                        nullptr, nullptr, M_, E_, DFF_);
}

// round 6
// speedup vs baseline: 6.7628x; 2.0170x over previous
#include <cuda_runtime.h>
#include <cuda_bf16.h>
#include <cuda_fp16.h>
#include <cstdint>

// Problem constants
#define B_   4
#define T_   2048
#define E_   1024
#define H_   16
#define HS_  64
#define DFF_ 4096
#define M_   (B_ * T_)   // 8192 rows

typedef __nv_bfloat16 bf16;

// ---------------------------------------------------------------------------
// Scratch (device globals)
// ---------------------------------------------------------------------------
__device__ __half g_a[(size_t)M_ * E_];     // fp16 activations (ln1/attn/ln2 out)
__device__ __half g_f[(size_t)M_ * DFF_];   // fp16 FFN hidden
// split-bf16 Q,K,V (attention stays high precision)
__device__ bf16 g_qh[(size_t)M_ * E_], g_ql[(size_t)M_ * E_];
__device__ bf16 g_kh[(size_t)M_ * E_], g_kl[(size_t)M_ * E_];
__device__ bf16 g_vh[(size_t)M_ * E_], g_vl[(size_t)M_ * E_];
// fp16 transposed weights [N,K]
__device__ __half g_wq[(size_t)E_ * E_], g_wk[(size_t)E_ * E_];
__device__ __half g_wv[(size_t)E_ * E_], g_wp[(size_t)E_ * E_];
__device__ __half g_w1[(size_t)E_ * DFF_], g_w2[(size_t)DFF_ * E_];

// ---------------------------------------------------------------------------
// Helpers
// ---------------------------------------------------------------------------
__device__ __forceinline__ uint32_t smem_u32(const void* p) {
    uint32_t a;
    asm("{ .reg .u64 t; cvta.to.shared.u64 t, %1; cvt.u32.u64 %0, t; }"
        : "=r"(a) : "l"(p));
    return a;
}

__device__ __forceinline__ void ldm_x4(uint32_t* r, uint32_t addr) {
    asm volatile("ldmatrix.sync.aligned.m8n8.x4.shared.b16 {%0,%1,%2,%3}, [%4];"
                 : "=r"(r[0]), "=r"(r[1]), "=r"(r[2]), "=r"(r[3]) : "r"(addr));
}
__device__ __forceinline__ void ldm_x4_t(uint32_t* r, uint32_t addr) {
    asm volatile("ldmatrix.sync.aligned.m8n8.x4.trans.shared.b16 {%0,%1,%2,%3}, [%4];"
                 : "=r"(r[0]), "=r"(r[1]), "=r"(r[2]), "=r"(r[3]) : "r"(addr));
}

// bf16 MMA (attention)
__device__ __forceinline__ void mma16816(float* c, const uint32_t* a, const uint32_t* b) {
    asm volatile(
        "mma.sync.aligned.m16n8k16.row.col.f32.bf16.bf16.f32 "
        "{%0,%1,%2,%3}, {%4,%5,%6,%7}, {%8,%9}, {%0,%1,%2,%3};"
        : "+f"(c[0]), "+f"(c[1]), "+f"(c[2]), "+f"(c[3])
        : "r"(a[0]), "r"(a[1]), "r"(a[2]), "r"(a[3]), "r"(b[0]), "r"(b[1]));
}
// fp16 MMA (GEMMs)
__device__ __forceinline__ void mma16816h(float* c, const uint32_t* a, const uint32_t* b) {
    asm volatile(
        "mma.sync.aligned.m16n8k16.row.col.f32.f16.f16.f32 "
        "{%0,%1,%2,%3}, {%4,%5,%6,%7}, {%8,%9}, {%0,%1,%2,%3};"
        : "+f"(c[0]), "+f"(c[1]), "+f"(c[2]), "+f"(c[3])
        : "r"(a[0]), "r"(a[1]), "r"(a[2]), "r"(a[3]), "r"(b[0]), "r"(b[1]));
}

#define CP_ASYNC16(dst, src) \
    asm volatile("cp.async.cg.shared.global [%0], [%1], 16;" :: "r"(dst), "l"(src))
#define CP_COMMIT() asm volatile("cp.async.commit_group;" ::: "memory")
#define CP_WAIT0() asm volatile("cp.async.wait_group 0;" ::: "memory")
#define CP_WAIT1() asm volatile("cp.async.wait_group 1;" ::: "memory")
#define CP_WAIT2() asm volatile("cp.async.wait_group 2;" ::: "memory")

__device__ __forceinline__ void split_pair(float a, float b, uint32_t& hi, uint32_t& lo) {
    __nv_bfloat162 h = __floats2bfloat162_rn(a, b);
    float ra = a - __bfloat162float(h.x);
    float rb = b - __bfloat162float(h.y);
    __nv_bfloat162 l = __floats2bfloat162_rn(ra, rb);
    hi = *reinterpret_cast<uint32_t*>(&h);
    lo = *reinterpret_cast<uint32_t*>(&l);
}

__device__ __forceinline__ uint32_t pack_h2(float a, float b) {
    __half2 h = __floats2half2_rn(a, b);
    return *reinterpret_cast<uint32_t*>(&h);
}

// generic 128-row x 128-byte tile cp.async with SW128 swizzle (256 threads)
template<typename T>
__device__ __forceinline__ void cpa_tile128(const T* __restrict__ g,
                                            int ldk, int k0, uint32_t sbase) {
    int tid = threadIdx.x;
    #pragma unroll
    for (int i = 0; i < 4; i++) {
        int idx = i * 256 + tid;
        int r = idx >> 3, c = idx & 7;
        uint32_t off = (uint32_t)(r * 128 + c * 16);
        off ^= (off >> 3) & 0x70;
        CP_ASYNC16(sbase + off, g + (size_t)r * ldk + k0 + c * 8);
    }
}

// ---------------------------------------------------------------------------
// LayerNorm -> fp16 output
// ---------------------------------------------------------------------------
__global__ __launch_bounds__(256)
void ln_h_kernel(const float* __restrict__ in, const float* __restrict__ gamma,
                 const float* __restrict__ beta, __half* __restrict__ O) {
    int row = blockIdx.x;
    int t = threadIdx.x;
    float4 v = ((const float4*)(in + (size_t)row * E_))[t];

    float s1 = v.x + v.y + v.z + v.w;
    float s2 = v.x * v.x + v.y * v.y + v.z * v.z + v.w * v.w;
    #pragma unroll
    for (int o = 16; o > 0; o >>= 1) {
        s1 += __shfl_xor_sync(0xffffffffu, s1, o);
        s2 += __shfl_xor_sync(0xffffffffu, s2, o);
    }
    __shared__ float red[64];
    int lane = t & 31, w = t >> 5;
    if (lane == 0) { red[w] = s1; red[w + 32] = s2; }
    __syncthreads();
    float ts1 = 0.f, ts2 = 0.f;
    #pragma unroll
    for (int i = 0; i < 8; i++) { ts1 += red[i]; ts2 += red[i + 32]; }

    float mu  = ts1 * (1.0f / E_);
    float var = ts2 * (1.0f / E_) - mu * mu;
    float rs  = rsqrtf(var + 1e-5f);

    float4 g4 = ((const float4*)gamma)[t];
    float4 b4 = ((const float4*)beta)[t];
    float o0 = (v.x - mu) * rs * g4.x + b4.x;
    float o1 = (v.y - mu) * rs * g4.y + b4.y;
    float o2 = (v.z - mu) * rs * g4.z + b4.z;
    float o3 = (v.w - mu) * rs * g4.w + b4.w;

    size_t idx = (size_t)row * E_ + t * 4;
    *reinterpret_cast<uint2*>(O + idx) = make_uint2(pack_h2(o0, o1), pack_h2(o2, o3));
}

// ---------------------------------------------------------------------------
// Weight transpose: W[K,N] fp32 -> T[N,K] fp16
// ---------------------------------------------------------------------------
__global__ void wtrans_h_kernel(const float* __restrict__ W,
                                __half* __restrict__ T, int K, int N) {
    __shared__ float t[32][33];
    int n0 = blockIdx.x * 32, k0 = blockIdx.y * 32;
    int tx = threadIdx.x, ty = threadIdx.y;
    #pragma unroll
    for (int i = 0; i < 32; i += 8)
        t[ty + i][tx] = W[(size_t)(k0 + ty + i) * N + n0 + tx];
    __syncthreads();
    #pragma unroll
    for (int i = 0; i < 32; i += 8) {
        size_t o = (size_t)(n0 + ty + i) * K + k0 + tx;
        T[o] = __float2half(t[tx][ty + i]);
    }
}

// ---------------------------------------------------------------------------
// fp16 single-term GEMM: C[M,N] = A[M,K] @ Wt[N,K]^T + bias (+relu/+res)
// 128x128 CTA, BK=64, 8 warps (2x4), 3-stage cp.async, 2 CTAs/SM.
// EPI: 1 = bias+relu -> fp16 ; 2 = bias+res -> fp32 ; 3 = bias -> bf16 split
// ---------------------------------------------------------------------------
#define HTILE_B  16384
#define HSTAGE_B (2 * HTILE_B)          // A, B
#define HGSMEM   (3 * HSTAGE_B + 128)

template<int EPI>
__device__ __forceinline__ void gemm_core_h(
        const __half* __restrict__ A, const __half* __restrict__ Bw,
        const float* __restrict__ bias, const float* __restrict__ res,
        float* __restrict__ Cf, __half* __restrict__ Hh,
        bf16* __restrict__ Ch, bf16* __restrict__ Cl,
        int M, int N, int K, int m0, int n0, uint32_t base) {
    int tid = threadIdx.x, lane = tid & 31, wid = tid >> 5;
    int warp_m = wid >> 2;
    int warp_n = wid & 3;

    const __half* Ab = A  + (size_t)m0 * K;
    const __half* Bb = Bw + (size_t)n0 * K;

    int amat = lane >> 3, arin = lane & 7;
    int aRow = warp_m * 64 + (amat & 1) * 8 + arin;
    int aChk = amat >> 1;
    // B ldm_x4: two n8 blocks per load
    int bRow4 = warp_n * 32 + ((lane >> 4) & 1) * 8 + (lane & 7);
    int bChk4 = (lane >> 3) & 1;

    float C[4][4][4];
    #pragma unroll
    for (int i = 0; i < 4; i++)
        #pragma unroll
        for (int j = 0; j < 4; j++)
            #pragma unroll
            for (int r = 0; r < 4; r++) C[i][j][r] = 0.f;

    int NT = K >> 6;

    cpa_tile128(Ab, K, 0, base);
    cpa_tile128(Bb, K, 0, base + HTILE_B);
    CP_COMMIT();
    cpa_tile128(Ab, K, 64, base + HSTAGE_B);
    cpa_tile128(Bb, K, 64, base + HSTAGE_B + HTILE_B);
    CP_COMMIT();

    for (int kt = 0; kt < NT; kt++) {
        if (kt + 1 < NT) { CP_WAIT1(); } else { CP_WAIT0(); }
        __syncthreads();

        uint32_t sc = base + (kt % 3) * HSTAGE_B;
        uint32_t sA = sc, sB = sc + HTILE_B;

        #pragma unroll
        for (int ks = 0; ks < 4; ks++) {
            uint32_t a4[4][4], b4[2][4];
            #pragma unroll
            for (int mi = 0; mi < 4; mi++) {
                uint32_t off = (uint32_t)((aRow + mi * 16) * 128 + (aChk + ks * 2) * 16);
                off ^= (off >> 3) & 0x70;
                ldm_x4(a4[mi], sA + off);
            }
            #pragma unroll
            for (int ni2 = 0; ni2 < 2; ni2++) {
                uint32_t off = (uint32_t)((bRow4 + ni2 * 16) * 128 + (bChk4 + ks * 2) * 16);
                off ^= (off >> 3) & 0x70;
                ldm_x4(b4[ni2], sB + off);
            }
            #pragma unroll
            for (int mi = 0; mi < 4; mi++) {
                #pragma unroll
                for (int ni2 = 0; ni2 < 2; ni2++) {
                    mma16816h(C[mi][2 * ni2],     a4[mi], &b4[ni2][0]);
                    mma16816h(C[mi][2 * ni2 + 1], a4[mi], &b4[ni2][2]);
                }
            }
        }

        if (kt + 2 < NT) {
            uint32_t sn = base + ((kt + 2) % 3) * HSTAGE_B;
            int k0 = (kt + 2) << 6;
            cpa_tile128(Ab, K, k0, sn);
            cpa_tile128(Bb, K, k0, sn + HTILE_B);
            CP_COMMIT();
        }
    }

    int gq = lane >> 2, tig = lane & 3;
    #pragma unroll
    for (int mi = 0; mi < 4; mi++) {
        #pragma unroll
        for (int ni = 0; ni < 4; ni++) {
            int m = m0 + warp_m * 64 + mi * 16 + gq;
            int n = n0 + warp_n * 32 + ni * 8 + tig * 2;
            float2 bv = *reinterpret_cast<const float2*>(&bias[n]);
            #pragma unroll
            for (int half_ = 0; half_ < 2; half_++) {
                int row = m + half_ * 8;
                float a0 = C[mi][ni][half_ * 2 + 0] + bv.x;
                float a1 = C[mi][ni][half_ * 2 + 1] + bv.y;
                size_t o = (size_t)row * N + n;
                if (EPI == 1) {
                    a0 = fmaxf(a0, 0.f); a1 = fmaxf(a1, 0.f);
                    *reinterpret_cast<uint32_t*>(Hh + o) = pack_h2(a0, a1);
                } else if (EPI == 3) {
                    uint32_t h01, l01;
                    split_pair(a0, a1, h01, l01);
                    *reinterpret_cast<uint32_t*>(Ch + o) = h01;
                    *reinterpret_cast<uint32_t*>(Cl + o) = l01;
                } else {
                    float2 rv = *reinterpret_cast<const float2*>(&res[o]);
                    a0 += rv.x; a1 += rv.y;
                    *reinterpret_cast<float2*>(&Cf[o]) = make_float2(a0, a1);
                }
            }
        }
    }
}

template<int EPI>
__global__ __launch_bounds__(256, 2)
void hgemm_kernel(const __half* __restrict__ A, const __half* __restrict__ Bw,
                  const float* __restrict__ bias, const float* __restrict__ res,
                  float* __restrict__ Cf, __half* __restrict__ Hh,
                  bf16* __restrict__ Ch, bf16* __restrict__ Cl,
                  int M, int N, int K) {
    extern __shared__ char dsm[];
    uint32_t base = smem_u32(dsm);
    base = (base + 127) & ~127u;
    gemm_core_h<EPI>(A, Bw, bias, res, Cf, Hh, Ch, Cl, M, N, K,
                     blockIdx.y * 128, blockIdx.x * 128, base);
}

struct QKVArgs {
    const __half* w[3];
    const float* bias[3];
    bf16* oh[3];
    bf16* ol[3];
};

__global__ __launch_bounds__(256, 2)
void qkv_kernel(const __half* __restrict__ A, QKVArgs args) {
    extern __shared__ char dsm[];
    uint32_t base = smem_u32(dsm);
    base = (base + 127) & ~127u;
    int z = blockIdx.z;
    gemm_core_h<3>(A, args.w[z], args.bias[z], nullptr, nullptr, nullptr,
                   args.oh[z], args.ol[z], M_, E_, E_,
                   blockIdx.y * 128, blockIdx.x * 128, base);
}

// ---------------------------------------------------------------------------
// Tensor-core causal flash attention (bf16 3-term inside), fp16 output.
// q-tile 128, 8 warps, 3-stage KV pipe; smem 32KB Q + 3x32KB = 128KB.
// ---------------------------------------------------------------------------
#define AQ_BYTES  32768
#define AST_SZ    32768
#define ATTN_SMEM (AQ_BYTES + 3 * AST_SZ + 256)
#define CEXP 0.18033688011112042f   // 0.125 * log2(e)

__device__ __forceinline__ void cpa_tile64(const bf16* __restrict__ g,
                                           uint32_t sbase) {
    int tid = threadIdx.x;   // 256 threads
    #pragma unroll
    for (int i = 0; i < 2; i++) {
        int idx = i * 256 + tid;
        int r = idx >> 3, c = idx & 7;
        uint32_t off = (uint32_t)(r * 128 + c * 16);
        off ^= (off >> 3) & 0x70;
        CP_ASYNC16(sbase + off, g + (size_t)r * E_ + c * 8);
    }
}

__global__ __launch_bounds__(256, 1)
void attn_mma_kernel(const bf16* __restrict__ Qh, const bf16* __restrict__ Ql,
                     const bf16* __restrict__ Kh, const bf16* __restrict__ Kl,
                     const bf16* __restrict__ Vh, const bf16* __restrict__ Vl,
                     __half* __restrict__ O) {
    extern __shared__ char dsm[];
    uint32_t base = smem_u32(dsm);
    base = (base + 127) & ~127u;

    int tid = threadIdx.x, lane = tid & 31, w = tid >> 5;
    int gq = lane >> 2, tig = lane & 3;
    int qi = gridDim.x - 1 - blockIdx.x;
    int q0 = qi * 128;
    int bh = blockIdx.y;
    int b = bh >> 4, h = bh & 15;
    size_t gbase = ((size_t)b * T_) * E_ + (size_t)h * HS_;

    int nt = (q0 >> 6) + 2;

    cpa_tile128(Qh + gbase + (size_t)q0 * E_, E_, 0, base);
    cpa_tile128(Ql + gbase + (size_t)q0 * E_, E_, 0, base + 16384);
    CP_COMMIT();
    #pragma unroll
    for (int st = 0; st < 2; st++) {
        uint32_t s = base + AQ_BYTES + st * AST_SZ;
        size_t koff = gbase + (size_t)(st * 64) * E_;
        cpa_tile64(Kh + koff, s + 0);
        cpa_tile64(Kl + koff, s + 8192);
        cpa_tile64(Vh + koff, s + 16384);
        cpa_tile64(Vl + koff, s + 24576);
        CP_COMMIT();
    }

    CP_WAIT2();
    __syncthreads();

    uint32_t qfh[4][4], qfl[4][4];
    {
        int arow = w * 16 + (lane & 7) + ((lane & 8) ? 8 : 0);
        int asel = (lane >> 4) & 1;
        #pragma unroll
        for (int ks = 0; ks < 4; ks++) {
            uint32_t off = (uint32_t)(arow * 128 + (ks * 2 + asel) * 16);
            off ^= (off >> 3) & 0x70;
            ldm_x4(qfh[ks], base + off);
            ldm_x4(qfl[ks], base + 16384 + off);
        }
    }

    float Oa[8][4];
    #pragma unroll
    for (int s = 0; s < 8; s++)
        #pragma unroll
        for (int r = 0; r < 4; r++) Oa[s][r] = 0.f;
    float m0r = -1e30f, m1r = -1e30f, l0r = 0.f, l1r = 0.f;

    int kRowBase = (lane & 7) + ((lane >= 16) ? 8 : 0);
    int kChkSel  = (lane & 8) ? 1 : 0;
    int vRowBase = (lane & 7) + ((lane & 8) ? 8 : 0);
    int vColB    = ((lane >= 16) ? 16 : 0);

    int maskFrom = q0 >> 6;

    for (int jt = 0; jt < nt; jt++) {
        if (jt + 1 < nt) { CP_WAIT1(); } else { CP_WAIT0(); }
        __syncthreads();

        uint32_t sc  = base + AQ_BYTES + (jt % 3) * AST_SZ;
        uint32_t sKh = sc, sKl = sc + 8192, sVh = sc + 16384, sVl = sc + 24576;

        float S[8][4];
        #pragma unroll
        for (int s = 0; s < 8; s++)
            #pragma unroll
            for (int r = 0; r < 4; r++) S[s][r] = 0.f;

        #pragma unroll
        for (int ks = 0; ks < 4; ks++) {
            #pragma unroll
            for (int g = 0; g < 4; g++) {
                uint32_t kh4[4], kl4[4];
                uint32_t off = (uint32_t)((g * 16 + kRowBase) * 128 +
                                          (ks * 2 + kChkSel) * 16);
                off ^= (off >> 3) & 0x70;
                ldm_x4(kh4, sKh + off);
                ldm_x4(kl4, sKl + off);
                mma16816(S[2 * g],     qfh[ks], &kh4[0]);
                mma16816(S[2 * g],     qfh[ks], &kl4[0]);
                mma16816(S[2 * g],     qfl[ks], &kh4[0]);
                mma16816(S[2 * g + 1], qfh[ks], &kh4[2]);
                mma16816(S[2 * g + 1], qfh[ks], &kl4[2]);
                mma16816(S[2 * g + 1], qfl[ks], &kh4[2]);
            }
        }

        if (jt >= maskFrom) {
            int qr0 = q0 + w * 16 + gq;
            int kc0 = jt * 64 + 2 * tig;
            #pragma unroll
            for (int s = 0; s < 8; s++) {
                int kc = kc0 + s * 8;
                if (kc     > qr0)     S[s][0] = -1e30f;
                if (kc + 1 > qr0)     S[s][1] = -1e30f;
                if (kc     > qr0 + 8) S[s][2] = -1e30f;
                if (kc + 1 > qr0 + 8) S[s][3] = -1e30f;
            }
        }

        float mx0 = -1e30f, mx1 = -1e30f;
        #pragma unroll
        for (int s = 0; s < 8; s++) {
            mx0 = fmaxf(mx0, fmaxf(S[s][0], S[s][1]));
            mx1 = fmaxf(mx1, fmaxf(S[s][2], S[s][3]));
        }
        mx0 = fmaxf(mx0, __shfl_xor_sync(0xffffffffu, mx0, 1));
        mx0 = fmaxf(mx0, __shfl_xor_sync(0xffffffffu, mx0, 2));
        mx1 = fmaxf(mx1, __shfl_xor_sync(0xffffffffu, mx1, 1));
        mx1 = fmaxf(mx1, __shfl_xor_sync(0xffffffffu, mx1, 2));

        float mn0 = fmaxf(m0r, mx0), mn1 = fmaxf(m1r, mx1);
        float al0 = exp2f((m0r - mn0) * CEXP);
        float al1 = exp2f((m1r - mn1) * CEXP);
        m0r = mn0; m1r = mn1;

        float ls0 = 0.f, ls1 = 0.f;
        #pragma unroll
        for (int s = 0; s < 8; s++) {
            S[s][0] = exp2f((S[s][0] - mn0) * CEXP);
            S[s][1] = exp2f((S[s][1] - mn0) * CEXP);
            S[s][2] = exp2f((S[s][2] - mn1) * CEXP);
            S[s][3] = exp2f((S[s][3] - mn1) * CEXP);
            ls0 += S[s][0] + S[s][1];
            ls1 += S[s][2] + S[s][3];
        }
        ls0 += __shfl_xor_sync(0xffffffffu, ls0, 1);
        ls0 += __shfl_xor_sync(0xffffffffu, ls0, 2);
        ls1 += __shfl_xor_sync(0xffffffffu, ls1, 1);
        ls1 += __shfl_xor_sync(0xffffffffu, ls1, 2);
        l0r = l0r * al0 + ls0;
        l1r = l1r * al1 + ls1;

        #pragma unroll
        for (int s = 0; s < 8; s++) {
            Oa[s][0] *= al0; Oa[s][1] *= al0;
            Oa[s][2] *= al1; Oa[s][3] *= al1;
        }

        uint32_t pah[4][4], pal[4][4];
        #pragma unroll
        for (int kk = 0; kk < 4; kk++) {
            split_pair(S[2 * kk][0],     S[2 * kk][1],     pah[kk][0], pal[kk][0]);
            split_pair(S[2 * kk][2],     S[2 * kk][3],     pah[kk][1], pal[kk][1]);
            split_pair(S[2 * kk + 1][0], S[2 * kk + 1][1], pah[kk][2], pal[kk][2]);
            split_pair(S[2 * kk + 1][2], S[2 * kk + 1][3], pah[kk][3], pal[kk][3]);
        }

        #pragma unroll
        for (int kk = 0; kk < 4; kk++) {
            #pragma unroll
            for (int g = 0; g < 4; g++) {
                uint32_t vh4[4], vl4[4];
                uint32_t off = (uint32_t)((kk * 16 + vRowBase) * 128 +
                                          g * 32 + vColB);
                off ^= (off >> 3) & 0x70;
                ldm_x4_t(vh4, sVh + off);
                ldm_x4_t(vl4, sVl + off);
                mma16816(Oa[2 * g],     pah[kk], &vh4[0]);
                mma16816(Oa[2 * g],     pah[kk], &vl4[0]);
                mma16816(Oa[2 * g],     pal[kk], &vh4[0]);
                mma16816(Oa[2 * g + 1], pah[kk], &vh4[2]);
                mma16816(Oa[2 * g + 1], pah[kk], &vl4[2]);
                mma16816(Oa[2 * g + 1], pal[kk], &vh4[2]);
            }
        }

        if (jt + 2 < nt) {
            uint32_t sn = base + AQ_BYTES + ((jt + 2) % 3) * AST_SZ;
            size_t koff = gbase + (size_t)((jt + 2) * 64) * E_;
            cpa_tile64(Kh + koff, sn + 0);
            cpa_tile64(Kl + koff, sn + 8192);
            cpa_tile64(Vh + koff, sn + 16384);
            cpa_tile64(Vl + koff, sn + 24576);
            CP_COMMIT();
        }
    }

    float inv0 = 1.0f / l0r, inv1 = 1.0f / l1r;
    int row0 = q0 + w * 16 + gq;
    #pragma unroll
    for (int s = 0; s < 8; s++) {
        int col = s * 8 + 2 * tig;
        size_t o0 = gbase + (size_t)row0 * E_ + col;
        size_t o1 = gbase + (size_t)(row0 + 8) * E_ + col;
        *reinterpret_cast<uint32_t*>(O + o0) = pack_h2(Oa[s][0] * inv0, Oa[s][1] * inv0);
        *reinterpret_cast<uint32_t*>(O + o1) = pack_h2(Oa[s][2] * inv1, Oa[s][3] * inv1);
    }
}

// ---------------------------------------------------------------------------
// Launch
// ---------------------------------------------------------------------------
extern "C" void kernel_launch(void* const* d_in, const int* in_sizes, int n_in,
                              void* d_out, int out_size) {
    (void)in_sizes; (void)n_in; (void)out_size;
    const float* x     = (const float*)d_in[0];
    const float* ln1_g = (const float*)d_in[1];
    const float* ln1_b = (const float*)d_in[2];
    const float* Wq    = (const float*)d_in[3];
    const float* bq    = (const float*)d_in[4];
    const float* Wk    = (const float*)d_in[5];
    const float* bk    = (const float*)d_in[6];
    const float* Wv    = (const float*)d_in[7];
    const float* bv    = (const float*)d_in[8];
    const float* Wp    = (const float*)d_in[9];
    const float* bp    = (const float*)d_in[10];
    const float* ln2_g = (const float*)d_in[11];
    const float* ln2_b = (const float*)d_in[12];
    const float* W1    = (const float*)d_in[13];
    const float* b1    = (const float*)d_in[14];
    const float* W2    = (const float*)d_in[15];
    const float* b2    = (const float*)d_in[16];
    float* out = (float*)d_out;

    __half *a, *f, *wq, *wk, *wv, *wp, *w1, *w2;
    bf16 *qh, *ql, *kh, *kl, *vh, *vl;
    cudaGetSymbolAddress((void**)&a, g_a);
    cudaGetSymbolAddress((void**)&f, g_f);
    cudaGetSymbolAddress((void**)&qh, g_qh);
    cudaGetSymbolAddress((void**)&ql, g_ql);
    cudaGetSymbolAddress((void**)&kh, g_kh);
    cudaGetSymbolAddress((void**)&kl, g_kl);
    cudaGetSymbolAddress((void**)&vh, g_vh);
    cudaGetSymbolAddress((void**)&vl, g_vl);
    cudaGetSymbolAddress((void**)&wq, g_wq);
    cudaGetSymbolAddress((void**)&wk, g_wk);
    cudaGetSymbolAddress((void**)&wv, g_wv);
    cudaGetSymbolAddress((void**)&wp, g_wp);
    cudaGetSymbolAddress((void**)&w1, g_w1);
    cudaGetSymbolAddress((void**)&w2, g_w2);

    cudaFuncSetAttribute(attn_mma_kernel,
                         cudaFuncAttributeMaxDynamicSharedMemorySize, ATTN_SMEM);
    cudaFuncSetAttribute(hgemm_kernel<1>,
                         cudaFuncAttributeMaxDynamicSharedMemorySize, HGSMEM);
    cudaFuncSetAttribute(hgemm_kernel<2>,
                         cudaFuncAttributeMaxDynamicSharedMemorySize, HGSMEM);
    cudaFuncSetAttribute(qkv_kernel,
                         cudaFuncAttributeMaxDynamicSharedMemorySize, HGSMEM);

    dim3 tb(32, 8);
    wtrans_h_kernel<<<dim3(E_ / 32, E_ / 32), tb>>>(Wq, wq, E_, E_);
    wtrans_h_kernel<<<dim3(E_ / 32, E_ / 32), tb>>>(Wk, wk, E_, E_);
    wtrans_h_kernel<<<dim3(E_ / 32, E_ / 32), tb>>>(Wv, wv, E_, E_);
    wtrans_h_kernel<<<dim3(E_ / 32, E_ / 32), tb>>>(Wp, wp, E_, E_);

    // ln1 -> fp16
    ln_h_kernel<<<M_, 256>>>(x, ln1_g, ln1_b, a);

    // fused QKV (fp16 in, bf16-split out)
    QKVArgs qa;
    qa.w[0] = wq; qa.bias[0] = bq; qa.oh[0] = qh; qa.ol[0] = ql;
    qa.w[1] = wk; qa.bias[1] = bk; qa.oh[1] = kh; qa.ol[1] = kl;
    qa.w[2] = wv; qa.bias[2] = bv; qa.oh[2] = vh; qa.ol[2] = vl;
    dim3 gQKV(E_ / 128, M_ / 128, 3);
    qkv_kernel<<<gQKV, 256, HGSMEM>>>(a, qa);

    wtrans_h_kernel<<<dim3(DFF_ / 32, E_ / 32), tb>>>(W1, w1, E_, DFF_);
    wtrans_h_kernel<<<dim3(E_ / 32, DFF_ / 32), tb>>>(W2, w2, DFF_, E_);

    // attention (bf16-3term inside, fp16 out into a)
    dim3 gA(T_ / 128, B_ * H_);
    attn_mma_kernel<<<gA, 256, ATTN_SMEM>>>(qh, ql, kh, kl, vh, vl, a);

    // proj + residual -> out (fp32)
    dim3 gE(E_ / 128, M_ / 128);
    hgemm_kernel<2><<<gE, 256, HGSMEM>>>(a, wp, bp, x, out, nullptr,
                                         nullptr, nullptr, M_, E_, E_);

    // ln2 -> fp16
    ln_h_kernel<<<M_, 256>>>(out, ln2_g, ln2_b, a);

    // FFN1 (relu -> fp16)
    dim3 gF1(DFF_ / 128, M_ / 128);
    hgemm_kernel<1><<<gF1, 256, HGSMEM>>>(a, w1, b1, nullptr, nullptr, f,
                                          nullptr, nullptr, M_, DFF_, E_);

    // FFN2 + residual (in place on out)
    hgemm_kernel<2><<<gE, 256, HGSMEM>>>(f, w2, b2, out, out, nullptr,
                                         nullptr, nullptr, M_, E_, DFF_);
}

// round 7
// speedup vs baseline: 8.3121x; 1.2291x over previous
#include <cuda_runtime.h>
#include <cuda_fp16.h>
#include <cstdint>

// Problem constants
#define B_   4
#define T_   2048
#define E_   1024
#define H_   16
#define HS_  64
#define DFF_ 4096
#define M_   (B_ * T_)   // 8192 rows

// ---------------------------------------------------------------------------
// Scratch (device globals)
// ---------------------------------------------------------------------------
__device__ __half g_a[(size_t)M_ * E_];     // fp16 activations (ln1/attn/ln2 out)
__device__ __half g_f[(size_t)M_ * DFF_];   // fp16 FFN hidden
__device__ __half g_q[(size_t)M_ * E_], g_k[(size_t)M_ * E_], g_v[(size_t)M_ * E_];
// fp16 transposed weights [N,K]
__device__ __half g_wq[(size_t)E_ * E_], g_wk[(size_t)E_ * E_];
__device__ __half g_wv[(size_t)E_ * E_], g_wp[(size_t)E_ * E_];
__device__ __half g_w1[(size_t)E_ * DFF_], g_w2[(size_t)DFF_ * E_];

// ---------------------------------------------------------------------------
// Helpers
// ---------------------------------------------------------------------------
__device__ __forceinline__ uint32_t smem_u32(const void* p) {
    uint32_t a;
    asm("{ .reg .u64 t; cvta.to.shared.u64 t, %1; cvt.u32.u64 %0, t; }"
        : "=r"(a) : "l"(p));
    return a;
}

__device__ __forceinline__ void ldm_x4(uint32_t* r, uint32_t addr) {
    asm volatile("ldmatrix.sync.aligned.m8n8.x4.shared.b16 {%0,%1,%2,%3}, [%4];"
                 : "=r"(r[0]), "=r"(r[1]), "=r"(r[2]), "=r"(r[3]) : "r"(addr));
}
__device__ __forceinline__ void ldm_x4_t(uint32_t* r, uint32_t addr) {
    asm volatile("ldmatrix.sync.aligned.m8n8.x4.trans.shared.b16 {%0,%1,%2,%3}, [%4];"
                 : "=r"(r[0]), "=r"(r[1]), "=r"(r[2]), "=r"(r[3]) : "r"(addr));
}

// fp16 MMA
__device__ __forceinline__ void mma16816h(float* c, const uint32_t* a, const uint32_t* b) {
    asm volatile(
        "mma.sync.aligned.m16n8k16.row.col.f32.f16.f16.f32 "
        "{%0,%1,%2,%3}, {%4,%5,%6,%7}, {%8,%9}, {%0,%1,%2,%3};"
        : "+f"(c[0]), "+f"(c[1]), "+f"(c[2]), "+f"(c[3])
        : "r"(a[0]), "r"(a[1]), "r"(a[2]), "r"(a[3]), "r"(b[0]), "r"(b[1]));
}

#define CP_ASYNC16(dst, src) \
    asm volatile("cp.async.cg.shared.global [%0], [%1], 16;" :: "r"(dst), "l"(src))
#define CP_COMMIT() asm volatile("cp.async.commit_group;" ::: "memory")
#define CP_WAIT0() asm volatile("cp.async.wait_group 0;" ::: "memory")
#define CP_WAIT1() asm volatile("cp.async.wait_group 1;" ::: "memory")
#define CP_WAIT2() asm volatile("cp.async.wait_group 2;" ::: "memory")

__device__ __forceinline__ uint32_t pack_h2(float a, float b) {
    __half2 h = __floats2half2_rn(a, b);
    return *reinterpret_cast<uint32_t*>(&h);
}

// generic 128-row x 128-byte tile cp.async with SW128 swizzle (256 threads)
template<typename T>
__device__ __forceinline__ void cpa_tile128(const T* __restrict__ g,
                                            int ldk, int k0, uint32_t sbase) {
    int tid = threadIdx.x;
    #pragma unroll
    for (int i = 0; i < 4; i++) {
        int idx = i * 256 + tid;
        int r = idx >> 3, c = idx & 7;
        uint32_t off = (uint32_t)(r * 128 + c * 16);
        off ^= (off >> 3) & 0x70;
        CP_ASYNC16(sbase + off, g + (size_t)r * ldk + k0 + c * 8);
    }
}

// 64-row x 128-byte tile (256 threads)
__device__ __forceinline__ void cpa_tile64(const __half* __restrict__ g,
                                           uint32_t sbase) {
    int tid = threadIdx.x;
    #pragma unroll
    for (int i = 0; i < 2; i++) {
        int idx = i * 256 + tid;
        int r = idx >> 3, c = idx & 7;
        uint32_t off = (uint32_t)(r * 128 + c * 16);
        off ^= (off >> 3) & 0x70;
        CP_ASYNC16(sbase + off, g + (size_t)r * E_ + c * 8);
    }
}

// ---------------------------------------------------------------------------
// LayerNorm -> fp16
// ---------------------------------------------------------------------------
__global__ __launch_bounds__(256)
void ln_h_kernel(const float* __restrict__ in, const float* __restrict__ gamma,
                 const float* __restrict__ beta, __half* __restrict__ O) {
    int row = blockIdx.x;
    int t = threadIdx.x;
    float4 v = ((const float4*)(in + (size_t)row * E_))[t];

    float s1 = v.x + v.y + v.z + v.w;
    float s2 = v.x * v.x + v.y * v.y + v.z * v.z + v.w * v.w;
    #pragma unroll
    for (int o = 16; o > 0; o >>= 1) {
        s1 += __shfl_xor_sync(0xffffffffu, s1, o);
        s2 += __shfl_xor_sync(0xffffffffu, s2, o);
    }
    __shared__ float red[64];
    int lane = t & 31, w = t >> 5;
    if (lane == 0) { red[w] = s1; red[w + 32] = s2; }
    __syncthreads();
    float ts1 = 0.f, ts2 = 0.f;
    #pragma unroll
    for (int i = 0; i < 8; i++) { ts1 += red[i]; ts2 += red[i + 32]; }

    float mu  = ts1 * (1.0f / E_);
    float var = ts2 * (1.0f / E_) - mu * mu;
    float rs  = rsqrtf(var + 1e-5f);

    float4 g4 = ((const float4*)gamma)[t];
    float4 b4 = ((const float4*)beta)[t];
    float o0 = (v.x - mu) * rs * g4.x + b4.x;
    float o1 = (v.y - mu) * rs * g4.y + b4.y;
    float o2 = (v.z - mu) * rs * g4.z + b4.z;
    float o3 = (v.w - mu) * rs * g4.w + b4.w;

    size_t idx = (size_t)row * E_ + t * 4;
    *reinterpret_cast<uint2*>(O + idx) = make_uint2(pack_h2(o0, o1), pack_h2(o2, o3));
}

// ---------------------------------------------------------------------------
// Weight transpose: W[K,N] fp32 -> T[N,K] fp16
// ---------------------------------------------------------------------------
__global__ void wtrans_h_kernel(const float* __restrict__ W,
                                __half* __restrict__ T, int K, int N) {
    __shared__ float t[32][33];
    int n0 = blockIdx.x * 32, k0 = blockIdx.y * 32;
    int tx = threadIdx.x, ty = threadIdx.y;
    #pragma unroll
    for (int i = 0; i < 32; i += 8)
        t[ty + i][tx] = W[(size_t)(k0 + ty + i) * N + n0 + tx];
    __syncthreads();
    #pragma unroll
    for (int i = 0; i < 32; i += 8) {
        size_t o = (size_t)(n0 + ty + i) * K + k0 + tx;
        T[o] = __float2half(t[tx][ty + i]);
    }
}

// ---------------------------------------------------------------------------
// fp16 single-term GEMM: C[M,N] = A[M,K] @ Wt[N,K]^T + bias (+relu/+res)
// 128x128 CTA, BK=64, 8 warps (2x4), 3-stage cp.async, 2 CTAs/SM.
// EPI: 0 = bias -> fp16 ; 1 = bias+relu -> fp16 ; 2 = bias+res -> fp32
// ---------------------------------------------------------------------------
#define HTILE_B  16384
#define HSTAGE_B (2 * HTILE_B)
#define HGSMEM   (3 * HSTAGE_B + 128)

template<int EPI>
__device__ __forceinline__ void gemm_core_h(
        const __half* __restrict__ A, const __half* __restrict__ Bw,
        const float* __restrict__ bias, const float* __restrict__ res,
        float* __restrict__ Cf, __half* __restrict__ Hh,
        int M, int N, int K, int m0, int n0, uint32_t base) {
    int tid = threadIdx.x, lane = tid & 31, wid = tid >> 5;
    int warp_m = wid >> 2;
    int warp_n = wid & 3;

    const __half* Ab = A  + (size_t)m0 * K;
    const __half* Bb = Bw + (size_t)n0 * K;

    int amat = lane >> 3, arin = lane & 7;
    int aRow = warp_m * 64 + (amat & 1) * 8 + arin;
    int aChk = amat >> 1;
    int bRow4 = warp_n * 32 + ((lane >> 4) & 1) * 8 + (lane & 7);
    int bChk4 = (lane >> 3) & 1;

    float C[4][4][4];
    #pragma unroll
    for (int i = 0; i < 4; i++)
        #pragma unroll
        for (int j = 0; j < 4; j++)
            #pragma unroll
            for (int r = 0; r < 4; r++) C[i][j][r] = 0.f;

    int NT = K >> 6;

    cpa_tile128(Ab, K, 0, base);
    cpa_tile128(Bb, K, 0, base + HTILE_B);
    CP_COMMIT();
    cpa_tile128(Ab, K, 64, base + HSTAGE_B);
    cpa_tile128(Bb, K, 64, base + HSTAGE_B + HTILE_B);
    CP_COMMIT();

    for (int kt = 0; kt < NT; kt++) {
        if (kt + 1 < NT) { CP_WAIT1(); } else { CP_WAIT0(); }
        __syncthreads();

        uint32_t sc = base + (kt % 3) * HSTAGE_B;
        uint32_t sA = sc, sB = sc + HTILE_B;

        #pragma unroll
        for (int ks = 0; ks < 4; ks++) {
            uint32_t a4[4][4], b4[2][4];
            #pragma unroll
            for (int mi = 0; mi < 4; mi++) {
                uint32_t off = (uint32_t)((aRow + mi * 16) * 128 + (aChk + ks * 2) * 16);
                off ^= (off >> 3) & 0x70;
                ldm_x4(a4[mi], sA + off);
            }
            #pragma unroll
            for (int ni2 = 0; ni2 < 2; ni2++) {
                uint32_t off = (uint32_t)((bRow4 + ni2 * 16) * 128 + (bChk4 + ks * 2) * 16);
                off ^= (off >> 3) & 0x70;
                ldm_x4(b4[ni2], sB + off);
            }
            #pragma unroll
            for (int mi = 0; mi < 4; mi++) {
                #pragma unroll
                for (int ni2 = 0; ni2 < 2; ni2++) {
                    mma16816h(C[mi][2 * ni2],     a4[mi], &b4[ni2][0]);
                    mma16816h(C[mi][2 * ni2 + 1], a4[mi], &b4[ni2][2]);
                }
            }
        }

        if (kt + 2 < NT) {
            uint32_t sn = base + ((kt + 2) % 3) * HSTAGE_B;
            int k0 = (kt + 2) << 6;
            cpa_tile128(Ab, K, k0, sn);
            cpa_tile128(Bb, K, k0, sn + HTILE_B);
            CP_COMMIT();
        }
    }

    int gq = lane >> 2, tig = lane & 3;
    #pragma unroll
    for (int mi = 0; mi < 4; mi++) {
        #pragma unroll
        for (int ni = 0; ni < 4; ni++) {
            int m = m0 + warp_m * 64 + mi * 16 + gq;
            int n = n0 + warp_n * 32 + ni * 8 + tig * 2;
            float2 bv = *reinterpret_cast<const float2*>(&bias[n]);
            #pragma unroll
            for (int half_ = 0; half_ < 2; half_++) {
                int row = m + half_ * 8;
                float a0 = C[mi][ni][half_ * 2 + 0] + bv.x;
                float a1 = C[mi][ni][half_ * 2 + 1] + bv.y;
                size_t o = (size_t)row * N + n;
                if (EPI == 0) {
                    *reinterpret_cast<uint32_t*>(Hh + o) = pack_h2(a0, a1);
                } else if (EPI == 1) {
                    a0 = fmaxf(a0, 0.f); a1 = fmaxf(a1, 0.f);
                    *reinterpret_cast<uint32_t*>(Hh + o) = pack_h2(a0, a1);
                } else {
                    float2 rv = *reinterpret_cast<const float2*>(&res[o]);
                    a0 += rv.x; a1 += rv.y;
                    *reinterpret_cast<float2*>(&Cf[o]) = make_float2(a0, a1);
                }
            }
        }
    }
}

template<int EPI>
__global__ __launch_bounds__(256, 2)
void hgemm_kernel(const __half* __restrict__ A, const __half* __restrict__ Bw,
                  const float* __restrict__ bias, const float* __restrict__ res,
                  float* __restrict__ Cf, __half* __restrict__ Hh,
                  int M, int N, int K) {
    extern __shared__ char dsm[];
    uint32_t base = smem_u32(dsm);
    base = (base + 127) & ~127u;
    gemm_core_h<EPI>(A, Bw, bias, res, Cf, Hh, M, N, K,
                     blockIdx.y * 128, blockIdx.x * 128, base);
}

struct QKVArgs {
    const __half* w[3];
    const float* bias[3];
    __half* o[3];
};

__global__ __launch_bounds__(256, 2)
void qkv_kernel(const __half* __restrict__ A, QKVArgs args) {
    extern __shared__ char dsm[];
    uint32_t base = smem_u32(dsm);
    base = (base + 127) & ~127u;
    int z = blockIdx.z;
    gemm_core_h<0>(A, args.w[z], args.bias[z], nullptr, nullptr, args.o[z],
                   M_, E_, E_, blockIdx.y * 128, blockIdx.x * 128, base);
}

// ---------------------------------------------------------------------------
// fp16 tensor-core causal flash attention.
// q-tile 128, 8 warps, 3-stage KV pipe; smem Q 16KB + 3x16KB = 64KB, 2 CTA/SM.
// ---------------------------------------------------------------------------
#define AQ_BYTES  16384
#define AST_SZ    16384            // K 8KB + V 8KB
#define ATTN_SMEM (AQ_BYTES + 3 * AST_SZ + 128)
#define CEXP 0.18033688011112042f  // 0.125 * log2(e)

__global__ __launch_bounds__(256, 2)
void attn_mma_kernel(const __half* __restrict__ Qg, const __half* __restrict__ Kg,
                     const __half* __restrict__ Vg, __half* __restrict__ O) {
    extern __shared__ char dsm[];
    uint32_t base = smem_u32(dsm);
    base = (base + 127) & ~127u;

    int tid = threadIdx.x, lane = tid & 31, w = tid >> 5;
    int gq = lane >> 2, tig = lane & 3;
    int qi = gridDim.x - 1 - blockIdx.x;   // largest-work tiles first
    int q0 = qi * 128;
    int bh = blockIdx.y;
    int b = bh >> 4, h = bh & 15;
    size_t gbase = ((size_t)b * T_) * E_ + (size_t)h * HS_;

    int nt = (q0 >> 6) + 2;

    cpa_tile128(Qg + gbase + (size_t)q0 * E_, E_, 0, base);
    CP_COMMIT();
    #pragma unroll
    for (int st = 0; st < 2; st++) {
        uint32_t s = base + AQ_BYTES + st * AST_SZ;
        size_t koff = gbase + (size_t)(st * 64) * E_;
        cpa_tile64(Kg + koff, s);
        cpa_tile64(Vg + koff, s + 8192);
        CP_COMMIT();
    }

    CP_WAIT2();
    __syncthreads();

    // Q A-fragments (registers)
    uint32_t qf[4][4];
    {
        int arow = w * 16 + (lane & 7) + ((lane & 8) ? 8 : 0);
        int asel = (lane >> 4) & 1;
        #pragma unroll
        for (int ks = 0; ks < 4; ks++) {
            uint32_t off = (uint32_t)(arow * 128 + (ks * 2 + asel) * 16);
            off ^= (off >> 3) & 0x70;
            ldm_x4(qf[ks], base + off);
        }
    }

    float Oa[8][4];
    #pragma unroll
    for (int s = 0; s < 8; s++)
        #pragma unroll
        for (int r = 0; r < 4; r++) Oa[s][r] = 0.f;
    float m0r = -1e30f, m1r = -1e30f, l0r = 0.f, l1r = 0.f;

    int kRowBase = (lane & 7) + ((lane >= 16) ? 8 : 0);
    int kChkSel  = (lane & 8) ? 1 : 0;
    int vRowBase = (lane & 7) + ((lane & 8) ? 8 : 0);
    int vColB    = ((lane >= 16) ? 16 : 0);

    int maskFrom = q0 >> 6;

    for (int jt = 0; jt < nt; jt++) {
        if (jt + 1 < nt) { CP_WAIT1(); } else { CP_WAIT0(); }
        __syncthreads();

        uint32_t sc = base + AQ_BYTES + (jt % 3) * AST_SZ;
        uint32_t sK = sc, sV = sc + 8192;

        // ---- S = Q K^T ----
        float S[8][4];
        #pragma unroll
        for (int s = 0; s < 8; s++)
            #pragma unroll
            for (int r = 0; r < 4; r++) S[s][r] = 0.f;

        #pragma unroll
        for (int ks = 0; ks < 4; ks++) {
            #pragma unroll
            for (int g = 0; g < 4; g++) {
                uint32_t k4[4];
                uint32_t off = (uint32_t)((g * 16 + kRowBase) * 128 +
                                          (ks * 2 + kChkSel) * 16);
                off ^= (off >> 3) & 0x70;
                ldm_x4(k4, sK + off);
                mma16816h(S[2 * g],     qf[ks], &k4[0]);
                mma16816h(S[2 * g + 1], qf[ks], &k4[2]);
            }
        }

        // ---- causal mask on edge tiles ----
        if (jt >= maskFrom) {
            int qr0 = q0 + w * 16 + gq;
            int kc0 = jt * 64 + 2 * tig;
            #pragma unroll
            for (int s = 0; s < 8; s++) {
                int kc = kc0 + s * 8;
                if (kc     > qr0)     S[s][0] = -1e30f;
                if (kc + 1 > qr0)     S[s][1] = -1e30f;
                if (kc     > qr0 + 8) S[s][2] = -1e30f;
                if (kc + 1 > qr0 + 8) S[s][3] = -1e30f;
            }
        }

        // ---- online softmax ----
        float mx0 = -1e30f, mx1 = -1e30f;
        #pragma unroll
        for (int s = 0; s < 8; s++) {
            mx0 = fmaxf(mx0, fmaxf(S[s][0], S[s][1]));
            mx1 = fmaxf(mx1, fmaxf(S[s][2], S[s][3]));
        }
        mx0 = fmaxf(mx0, __shfl_xor_sync(0xffffffffu, mx0, 1));
        mx0 = fmaxf(mx0, __shfl_xor_sync(0xffffffffu, mx0, 2));
        mx1 = fmaxf(mx1, __shfl_xor_sync(0xffffffffu, mx1, 1));
        mx1 = fmaxf(mx1, __shfl_xor_sync(0xffffffffu, mx1, 2));

        float mn0 = fmaxf(m0r, mx0), mn1 = fmaxf(m1r, mx1);
        float al0 = exp2f((m0r - mn0) * CEXP);
        float al1 = exp2f((m1r - mn1) * CEXP);
        m0r = mn0; m1r = mn1;

        float ls0 = 0.f, ls1 = 0.f;
        #pragma unroll
        for (int s = 0; s < 8; s++) {
            S[s][0] = exp2f((S[s][0] - mn0) * CEXP);
            S[s][1] = exp2f((S[s][1] - mn0) * CEXP);
            S[s][2] = exp2f((S[s][2] - mn1) * CEXP);
            S[s][3] = exp2f((S[s][3] - mn1) * CEXP);
            ls0 += S[s][0] + S[s][1];
            ls1 += S[s][2] + S[s][3];
        }
        ls0 += __shfl_xor_sync(0xffffffffu, ls0, 1);
        ls0 += __shfl_xor_sync(0xffffffffu, ls0, 2);
        ls1 += __shfl_xor_sync(0xffffffffu, ls1, 1);
        ls1 += __shfl_xor_sync(0xffffffffu, ls1, 2);
        l0r = l0r * al0 + ls0;
        l1r = l1r * al1 + ls1;

        #pragma unroll
        for (int s = 0; s < 8; s++) {
            Oa[s][0] *= al0; Oa[s][1] *= al0;
            Oa[s][2] *= al1; Oa[s][3] *= al1;
        }

        // ---- pack P into fp16 A-fragments ----
        uint32_t pa[4][4];
        #pragma unroll
        for (int kk = 0; kk < 4; kk++) {
            pa[kk][0] = pack_h2(S[2 * kk][0],     S[2 * kk][1]);
            pa[kk][1] = pack_h2(S[2 * kk][2],     S[2 * kk][3]);
            pa[kk][2] = pack_h2(S[2 * kk + 1][0], S[2 * kk + 1][1]);
            pa[kk][3] = pack_h2(S[2 * kk + 1][2], S[2 * kk + 1][3]);
        }

        // ---- O += P V ----
        #pragma unroll
        for (int kk = 0; kk < 4; kk++) {
            #pragma unroll
            for (int g = 0; g < 4; g++) {
                uint32_t v4[4];
                uint32_t off = (uint32_t)((kk * 16 + vRowBase) * 128 +
                                          g * 32 + vColB);
                off ^= (off >> 3) & 0x70;
                ldm_x4_t(v4, sV + off);
                mma16816h(Oa[2 * g],     pa[kk], &v4[0]);
                mma16816h(Oa[2 * g + 1], pa[kk], &v4[2]);
            }
        }

        if (jt + 2 < nt) {
            uint32_t sn = base + AQ_BYTES + ((jt + 2) % 3) * AST_SZ;
            size_t koff = gbase + (size_t)((jt + 2) * 64) * E_;
            cpa_tile64(Kg + koff, sn);
            cpa_tile64(Vg + koff, sn + 8192);
            CP_COMMIT();
        }
    }

    float inv0 = 1.0f / l0r, inv1 = 1.0f / l1r;
    int row0 = q0 + w * 16 + gq;
    #pragma unroll
    for (int s = 0; s < 8; s++) {
        int col = s * 8 + 2 * tig;
        size_t o0 = gbase + (size_t)row0 * E_ + col;
        size_t o1 = gbase + (size_t)(row0 + 8) * E_ + col;
        *reinterpret_cast<uint32_t*>(O + o0) = pack_h2(Oa[s][0] * inv0, Oa[s][1] * inv0);
        *reinterpret_cast<uint32_t*>(O + o1) = pack_h2(Oa[s][2] * inv1, Oa[s][3] * inv1);
    }
}

// ---------------------------------------------------------------------------
// Launch
// ---------------------------------------------------------------------------
extern "C" void kernel_launch(void* const* d_in, const int* in_sizes, int n_in,
                              void* d_out, int out_size) {
    (void)in_sizes; (void)n_in; (void)out_size;
    const float* x     = (const float*)d_in[0];
    const float* ln1_g = (const float*)d_in[1];
    const float* ln1_b = (const float*)d_in[2];
    const float* Wq    = (const float*)d_in[3];
    const float* bq    = (const float*)d_in[4];
    const float* Wk    = (const float*)d_in[5];
    const float* bk    = (const float*)d_in[6];
    const float* Wv    = (const float*)d_in[7];
    const float* bv    = (const float*)d_in[8];
    const float* Wp    = (const float*)d_in[9];
    const float* bp    = (const float*)d_in[10];
    const float* ln2_g = (const float*)d_in[11];
    const float* ln2_b = (const float*)d_in[12];
    const float* W1    = (const float*)d_in[13];
    const float* b1    = (const float*)d_in[14];
    const float* W2    = (const float*)d_in[15];
    const float* b2    = (const float*)d_in[16];
    float* out = (float*)d_out;

    __half *a, *f, *q, *k, *v, *wq, *wk, *wv, *wp, *w1, *w2;
    cudaGetSymbolAddress((void**)&a, g_a);
    cudaGetSymbolAddress((void**)&f, g_f);
    cudaGetSymbolAddress((void**)&q, g_q);
    cudaGetSymbolAddress((void**)&k, g_k);
    cudaGetSymbolAddress((void**)&v, g_v);
    cudaGetSymbolAddress((void**)&wq, g_wq);
    cudaGetSymbolAddress((void**)&wk, g_wk);
    cudaGetSymbolAddress((void**)&wv, g_wv);
    cudaGetSymbolAddress((void**)&wp, g_wp);
    cudaGetSymbolAddress((void**)&w1, g_w1);
    cudaGetSymbolAddress((void**)&w2, g_w2);

    cudaFuncSetAttribute(attn_mma_kernel,
                         cudaFuncAttributeMaxDynamicSharedMemorySize, ATTN_SMEM);
    cudaFuncSetAttribute(hgemm_kernel<1>,
                         cudaFuncAttributeMaxDynamicSharedMemorySize, HGSMEM);
    cudaFuncSetAttribute(hgemm_kernel<2>,
                         cudaFuncAttributeMaxDynamicSharedMemorySize, HGSMEM);
    cudaFuncSetAttribute(qkv_kernel,
                         cudaFuncAttributeMaxDynamicSharedMemorySize, HGSMEM);

    dim3 tb(32, 8);
    wtrans_h_kernel<<<dim3(E_ / 32, E_ / 32), tb>>>(Wq, wq, E_, E_);
    wtrans_h_kernel<<<dim3(E_ / 32, E_ / 32), tb>>>(Wk, wk, E_, E_);
    wtrans_h_kernel<<<dim3(E_ / 32, E_ / 32), tb>>>(Wv, wv, E_, E_);
    wtrans_h_kernel<<<dim3(E_ / 32, E_ / 32), tb>>>(Wp, wp, E_, E_);

    // ln1 -> fp16
    ln_h_kernel<<<M_, 256>>>(x, ln1_g, ln1_b, a);

    // fused QKV (fp16 in/out)
    QKVArgs qa;
    qa.w[0] = wq; qa.bias[0] = bq; qa.o[0] = q;
    qa.w[1] = wk; qa.bias[1] = bk; qa.o[1] = k;
    qa.w[2] = wv; qa.bias[2] = bv; qa.o[2] = v;
    dim3 gQKV(E_ / 128, M_ / 128, 3);
    qkv_kernel<<<gQKV, 256, HGSMEM>>>(a, qa);

    wtrans_h_kernel<<<dim3(DFF_ / 32, E_ / 32), tb>>>(W1, w1, E_, DFF_);
    wtrans_h_kernel<<<dim3(E_ / 32, DFF_ / 32), tb>>>(W2, w2, DFF_, E_);

    // fp16 attention -> a
    dim3 gA(T_ / 128, B_ * H_);
    attn_mma_kernel<<<gA, 256, ATTN_SMEM>>>(q, k, v, a);

    // proj + residual -> out (fp32)
    dim3 gE(E_ / 128, M_ / 128);
    hgemm_kernel<2><<<gE, 256, HGSMEM>>>(a, wp, bp, x, out, nullptr,
                                         M_, E_, E_);

    // ln2 -> fp16
    ln_h_kernel<<<M_, 256>>>(out, ln2_g, ln2_b, a);

    // FFN1 (relu -> fp16)
    dim3 gF1(DFF_ / 128, M_ / 128);
    hgemm_kernel<1><<<gF1, 256, HGSMEM>>>(a, w1, b1, nullptr, nullptr, f,
                                          M_, DFF_, E_);

    // FFN2 + residual (in place on out)
    hgemm_kernel<2><<<gE, 256, HGSMEM>>>(f, w2, b2, out, out, nullptr,
                                         M_, E_, DFF_);
}